// round 1
// baseline (speedup 1.0000x reference)
#include <cuda_runtime.h>
#include <math.h>

// Problem constants
#define Bc   4
#define Sc   1024
#define Dc   1024
#define Hc   16
#define DKc  64
#define Mc   (Bc*Sc)        // 4096 rows
#define BHc  (Bc*Hc)        // 64 batch-heads
#define YSIZE (Bc*Sc*Dc)    // 4194304 floats (y), p follows in d_out

// Scratch (device globals — no runtime allocation allowed)
__device__ float g_Q[Mc*Dc];     // [BH, S, DK] head layout
__device__ float g_K[Mc*Dc];
__device__ float g_V[Mc*Dc];
__device__ float g_att[Mc*Dc];   // [b*s, h*dk]
__device__ float g_fc[Mc*Dc];    // fc + residual, pre-LN

// ---------------------------------------------------------------------------
// 128x128x8 SGEMM, M=4096, N=1024, K=1024 fixed.
// mode 0/1/2 : C = A @ W, scatter to g_Q/g_K/g_V in [b,h,s,dk] layout
// mode 3     : C = g_att @ W + bias + resid -> g_fc (plain row-major)
// ---------------------------------------------------------------------------
__global__ __launch_bounds__(256) void gemm128(const float* __restrict__ A,
                                               const float* __restrict__ W,
                                               const float* __restrict__ bias,
                                               const float* __restrict__ resid,
                                               int mode)
{
    __shared__ float As[8][128];
    __shared__ float Bs[8][128];

    const float* Ap = (mode == 3) ? g_att : A;
    float* out;
    if      (mode == 0) out = g_Q;
    else if (mode == 1) out = g_K;
    else if (mode == 2) out = g_V;
    else                out = g_fc;

    const int tid  = threadIdx.x;
    const int brow = blockIdx.y * 128;
    const int bcol = blockIdx.x * 128;
    const int tx = tid & 15;
    const int ty = tid >> 4;

    float acc[8][8];
#pragma unroll
    for (int i = 0; i < 8; i++)
#pragma unroll
        for (int j = 0; j < 8; j++) acc[i][j] = 0.0f;

    const int ar = tid >> 1;            // 0..127
    const int ac = (tid & 1) << 2;      // 0 or 4
    const float* Aload = Ap + (size_t)(brow + ar) * 1024 + ac;
    const int br = tid >> 5;            // 0..7
    const int bc = (tid & 31) << 2;     // 0..124
    const float* Wload = W + (size_t)br * 1024 + bcol + bc;

    for (int k0 = 0; k0 < 1024; k0 += 8) {
        float4 a4 = *(const float4*)(Aload + k0);
        As[ac + 0][ar] = a4.x;
        As[ac + 1][ar] = a4.y;
        As[ac + 2][ar] = a4.z;
        As[ac + 3][ar] = a4.w;
        *(float4*)&Bs[br][bc] = *(const float4*)(Wload + (size_t)k0 * 1024);
        __syncthreads();
#pragma unroll
        for (int k = 0; k < 8; k++) {
            float a[8], b[8];
            *(float4*)&a[0] = *(const float4*)&As[k][ty * 8];
            *(float4*)&a[4] = *(const float4*)&As[k][ty * 8 + 4];
            *(float4*)&b[0] = *(const float4*)&Bs[k][tx * 8];
            *(float4*)&b[4] = *(const float4*)&Bs[k][tx * 8 + 4];
#pragma unroll
            for (int i = 0; i < 8; i++)
#pragma unroll
                for (int j = 0; j < 8; j++) acc[i][j] = fmaf(a[i], b[j], acc[i][j]);
        }
        __syncthreads();
    }

    if (mode < 3) {
        // scatter to head layout: n -> (h, dk); tx*8 block stays within one head
        const int n0  = bcol + tx * 8;
        const int h   = n0 >> 6;
        const int dk0 = n0 & 63;
#pragma unroll
        for (int i = 0; i < 8; i++) {
            const int m = brow + ty * 8 + i;
            const int b = m >> 10;
            const int s = m & 1023;
            float* o = out + (((size_t)(b * Hc + h) * Sc + s) * DKc + dk0);
            float4 v0 = make_float4(acc[i][0], acc[i][1], acc[i][2], acc[i][3]);
            float4 v1 = make_float4(acc[i][4], acc[i][5], acc[i][6], acc[i][7]);
            *(float4*)(o)     = v0;
            *(float4*)(o + 4) = v1;
        }
    } else {
        const int n0 = bcol + tx * 8;
        float4 bi0 = *(const float4*)(bias + n0);
        float4 bi1 = *(const float4*)(bias + n0 + 4);
#pragma unroll
        for (int i = 0; i < 8; i++) {
            const int m = brow + ty * 8 + i;
            const size_t off = (size_t)m * 1024 + n0;
            float4 r0 = *(const float4*)(resid + off);
            float4 r1 = *(const float4*)(resid + off + 4);
            float4 v0 = make_float4(acc[i][0] + bi0.x + r0.x, acc[i][1] + bi0.y + r0.y,
                                    acc[i][2] + bi0.z + r0.z, acc[i][3] + bi0.w + r0.w);
            float4 v1 = make_float4(acc[i][4] + bi1.x + r1.x, acc[i][5] + bi1.y + r1.y,
                                    acc[i][6] + bi1.z + r1.z, acc[i][7] + bi1.w + r1.w);
            *(float4*)(out + off)     = v0;
            *(float4*)(out + off + 4) = v1;
        }
    }
}

// ---------------------------------------------------------------------------
// scores[bh, q, k] = (Q.Kt)/8 + relation, masked -> NEG. Raw scores into p buf.
// Tiles: 128 q-rows x 64 k-cols, full DK=64 in smem. Grid (16, 8, 64).
// ---------------------------------------------------------------------------
__global__ __launch_bounds__(256) void scores_kernel(const float* __restrict__ rel,
                                                     const int*   __restrict__ mask,
                                                     float* __restrict__ p)
{
    __shared__ float Qs[64][128];   // [k][q]
    __shared__ float Ks[64][64];    // [k][n]

    const int bh = blockIdx.z;
    const int q0 = blockIdx.y * 128;
    const int n0 = blockIdx.x * 64;
    const float* Qb = g_Q + (size_t)bh * Sc * DKc;
    const float* Kb = g_K + (size_t)bh * Sc * DKc;
    const int tid = threadIdx.x;

#pragma unroll
    for (int it = 0; it < 8; it++) {
        int lin = it * 1024 + tid * 4;
        int r = lin >> 6;
        int c = lin & 63;
        float4 v = *(const float4*)(Qb + (size_t)(q0 + r) * 64 + c);
        Qs[c + 0][r] = v.x; Qs[c + 1][r] = v.y; Qs[c + 2][r] = v.z; Qs[c + 3][r] = v.w;
    }
#pragma unroll
    for (int it = 0; it < 4; it++) {
        int lin = it * 1024 + tid * 4;
        int r = lin >> 6;
        int c = lin & 63;
        float4 v = *(const float4*)(Kb + (size_t)(n0 + r) * 64 + c);
        Ks[c + 0][r] = v.x; Ks[c + 1][r] = v.y; Ks[c + 2][r] = v.z; Ks[c + 3][r] = v.w;
    }
    __syncthreads();

    const int tx = tid & 15;
    const int ty = tid >> 4;
    float acc[8][4];
#pragma unroll
    for (int i = 0; i < 8; i++)
#pragma unroll
        for (int j = 0; j < 4; j++) acc[i][j] = 0.0f;

#pragma unroll 8
    for (int k = 0; k < 64; k++) {
        float a[8], b[4];
        *(float4*)&a[0] = *(const float4*)&Qs[k][ty * 8];
        *(float4*)&a[4] = *(const float4*)&Qs[k][ty * 8 + 4];
        *(float4*)&b[0] = *(const float4*)&Ks[k][tx * 4];
#pragma unroll
        for (int i = 0; i < 8; i++)
#pragma unroll
            for (int j = 0; j < 4; j++) acc[i][j] = fmaf(a[i], b[j], acc[i][j]);
    }

    const int b = bh >> 4;
#pragma unroll
    for (int i = 0; i < 8; i++) {
        const int q = q0 + ty * 8 + i;
        const size_t ridx = ((size_t)b * Sc + q) * Sc + n0 + tx * 4;
        float4 r4 = *(const float4*)(rel + ridx);
        int4   m4 = *(const int4*)(mask + ridx);
        float4 o;
        o.x = m4.x ? -1e9f : fmaf(acc[i][0], 0.125f, r4.x);
        o.y = m4.y ? -1e9f : fmaf(acc[i][1], 0.125f, r4.y);
        o.z = m4.z ? -1e9f : fmaf(acc[i][2], 0.125f, r4.z);
        o.w = m4.w ? -1e9f : fmaf(acc[i][3], 0.125f, r4.w);
        *(float4*)(p + ((size_t)bh * Sc + q) * Sc + n0 + tx * 4) = o;
    }
}

// ---------------------------------------------------------------------------
// In-place row softmax over 1024-element rows. Grid = 65536 blocks x 256 thr.
// ---------------------------------------------------------------------------
__global__ __launch_bounds__(256) void softmax_kernel(float* __restrict__ p)
{
    __shared__ float smax[8];
    __shared__ float ssum[8];
    const size_t row = blockIdx.x;
    float* pr = p + row * 1024;
    const int tid  = threadIdx.x;
    const int lane = tid & 31;
    const int w    = tid >> 5;

    float4 v = *(float4*)(pr + tid * 4);
    float m = fmaxf(fmaxf(v.x, v.y), fmaxf(v.z, v.w));
#pragma unroll
    for (int o = 16; o > 0; o >>= 1) m = fmaxf(m, __shfl_xor_sync(0xffffffffu, m, o));
    if (lane == 0) smax[w] = m;
    __syncthreads();
    m = smax[0];
#pragma unroll
    for (int i = 1; i < 8; i++) m = fmaxf(m, smax[i]);

    v.x = expf(v.x - m);
    v.y = expf(v.y - m);
    v.z = expf(v.z - m);
    v.w = expf(v.w - m);
    float s = v.x + v.y + v.z + v.w;
#pragma unroll
    for (int o = 16; o > 0; o >>= 1) s += __shfl_xor_sync(0xffffffffu, s, o);
    if (lane == 0) ssum[w] = s;
    __syncthreads();
    s = ssum[0];
#pragma unroll
    for (int i = 1; i < 8; i++) s += ssum[i];

    const float inv = 1.0f / s;
    v.x *= inv; v.y *= inv; v.z *= inv; v.w *= inv;
    *(float4*)(pr + tid * 4) = v;
}

// ---------------------------------------------------------------------------
// att = P @ V per batch-head. M=1024, N=64, K=1024. Output -> g_att[b*s, h*dk].
// Tiles: 128 x 64 x 16. Grid (8, 1, 64).
// ---------------------------------------------------------------------------
__global__ __launch_bounds__(256) void att_kernel(const float* __restrict__ p)
{
    __shared__ float Ps[16][128];   // [k][q]
    __shared__ float Vs[16][64];    // [k][dk]

    const int bh = blockIdx.z;
    const int q0 = blockIdx.x * 128;
    const float* Pb = p   + (size_t)bh * Sc * Sc;
    const float* Vb = g_V + (size_t)bh * Sc * DKc;
    const int tid = threadIdx.x;
    const int tx = tid & 15;
    const int ty = tid >> 4;

    float acc[8][4];
#pragma unroll
    for (int i = 0; i < 8; i++)
#pragma unroll
        for (int j = 0; j < 4; j++) acc[i][j] = 0.0f;

    for (int k0 = 0; k0 < 1024; k0 += 16) {
#pragma unroll
        for (int it = 0; it < 2; it++) {
            int lin = it * 1024 + tid * 4;
            int r = lin >> 4;           // 0..127
            int c = lin & 15;           // 0,4,8,12
            float4 v = *(const float4*)(Pb + (size_t)(q0 + r) * 1024 + k0 + c);
            Ps[c + 0][r] = v.x; Ps[c + 1][r] = v.y; Ps[c + 2][r] = v.z; Ps[c + 3][r] = v.w;
        }
        {
            int r = tid >> 4;
            int c = (tid & 15) * 4;
            *(float4*)&Vs[r][c] = *(const float4*)(Vb + (size_t)(k0 + r) * 64 + c);
        }
        __syncthreads();
#pragma unroll
        for (int k = 0; k < 16; k++) {
            float a[8], b[4];
            *(float4*)&a[0] = *(const float4*)&Ps[k][ty * 8];
            *(float4*)&a[4] = *(const float4*)&Ps[k][ty * 8 + 4];
            *(float4*)&b[0] = *(const float4*)&Vs[k][tx * 4];
#pragma unroll
            for (int i = 0; i < 8; i++)
#pragma unroll
                for (int j = 0; j < 4; j++) acc[i][j] = fmaf(a[i], b[j], acc[i][j]);
        }
        __syncthreads();
    }

    const int b = bh >> 4;
    const int h = bh & 15;
#pragma unroll
    for (int i = 0; i < 8; i++) {
        const int q = q0 + ty * 8 + i;
        float4 v = make_float4(acc[i][0], acc[i][1], acc[i][2], acc[i][3]);
        *(float4*)(g_att + ((size_t)(b * Sc + q)) * 1024 + h * 64 + tx * 4) = v;
    }
}

// ---------------------------------------------------------------------------
// LayerNorm over rows of g_fc -> y. Grid 4096 x 256.
// ---------------------------------------------------------------------------
__global__ __launch_bounds__(256) void ln_kernel(const float* __restrict__ g,
                                                 const float* __restrict__ bta,
                                                 float* __restrict__ y)
{
    __shared__ float s1[8];
    __shared__ float s2[8];
    const int row = blockIdx.x;
    const int tid  = threadIdx.x;
    const int lane = tid & 31;
    const int w    = tid >> 5;
    const float* xr = g_fc + (size_t)row * 1024;

    float4 v = *(const float4*)(xr + tid * 4);
    float s = v.x + v.y + v.z + v.w;
    float q = v.x * v.x + v.y * v.y + v.z * v.z + v.w * v.w;
#pragma unroll
    for (int o = 16; o > 0; o >>= 1) {
        s += __shfl_xor_sync(0xffffffffu, s, o);
        q += __shfl_xor_sync(0xffffffffu, q, o);
    }
    if (lane == 0) { s1[w] = s; s2[w] = q; }
    __syncthreads();
    s = 0.0f; q = 0.0f;
#pragma unroll
    for (int i = 0; i < 8; i++) { s += s1[i]; q += s2[i]; }

    const float mu  = s * (1.0f / 1024.0f);
    const float var = q * (1.0f / 1024.0f) - mu * mu;
    const float rs  = rsqrtf(var + 1e-5f);

    float4 gg = *(const float4*)(g   + tid * 4);
    float4 bb = *(const float4*)(bta + tid * 4);
    float4 o;
    o.x = (v.x - mu) * rs * gg.x + bb.x;
    o.y = (v.y - mu) * rs * gg.y + bb.y;
    o.z = (v.z - mu) * rs * gg.z + bb.z;
    o.w = (v.w - mu) * rs * gg.w + bb.w;
    *(float4*)(y + (size_t)row * 1024 + tid * 4) = o;
}

// ---------------------------------------------------------------------------
extern "C" void kernel_launch(void* const* d_in, const int* in_sizes, int n_in,
                              void* d_out, int out_size)
{
    const float* query    = (const float*)d_in[0];
    const float* key      = (const float*)d_in[1];
    const float* value    = (const float*)d_in[2];
    const int*   mask     = (const int*)  d_in[3];
    const float* relation = (const float*)d_in[4];
    const float* Wq       = (const float*)d_in[5];
    const float* Wk       = (const float*)d_in[6];
    const float* Wv       = (const float*)d_in[7];
    const float* fc_w     = (const float*)d_in[8];
    const float* fc_b     = (const float*)d_in[9];
    const float* ln_g     = (const float*)d_in[10];
    const float* ln_b     = (const float*)d_in[11];

    float* y = (float*)d_out;
    float* p = y + (size_t)YSIZE;

    dim3 gproj(Dc / 128, Mc / 128);                 // (8, 32)
    gemm128<<<gproj, 256>>>(query, Wq, nullptr, nullptr, 0);
    gemm128<<<gproj, 256>>>(key,   Wk, nullptr, nullptr, 1);
    gemm128<<<gproj, 256>>>(value, Wv, nullptr, nullptr, 2);

    scores_kernel<<<dim3(Sc / 64, Sc / 128, BHc), 256>>>(relation, mask, p);
    softmax_kernel<<<BHc * Sc, 256>>>(p);
    att_kernel<<<dim3(Sc / 128, 1, BHc), 256>>>(p);

    gemm128<<<gproj, 256>>>(nullptr, fc_w, fc_b, query, 3);
    ln_kernel<<<Mc, 256>>>(ln_g, ln_b, y);
}

// round 4
// speedup vs baseline: 2.1010x; 2.1010x over previous
#include <cuda_runtime.h>
#include <cuda_bf16.h>
#include <math.h>
#include <stdint.h>

#define Bc   4
#define Sc   1024
#define Dc   1024
#define Hc   16
#define DKc  64
#define Mc   (Bc*Sc)        // 4096
#define BHc  (Bc*Hc)        // 64
#define YSIZE (Bc*Sc*Dc)

// ---------------- device scratch (no runtime allocation) ----------------
__device__ __nv_bfloat16 g_Ah[Mc*Dc],  g_Al[Mc*Dc];      // current GEMM A (hi/lo)
__device__ __nv_bfloat16 g_Qh[Mc*Dc],  g_Ql[Mc*Dc];      // [bh][s][dk]
__device__ __nv_bfloat16 g_Kh[Mc*Dc],  g_Kl[Mc*Dc];      // [bh][s][dk]
__device__ __nv_bfloat16 g_VTh[Mc*Dc], g_VTl[Mc*Dc];     // [bh][dk][s]
__device__ __nv_bfloat16 g_atth[Mc*Dc], g_attl[Mc*Dc];   // [m][h*dk]
__device__ float g_fc[Mc*Dc];                             // fc + resid (pre-LN)
__device__ __nv_bfloat16 g_WTh[4][Dc*Dc], g_WTl[4][Dc*Dc]; // WT[n][k] hi/lo

// ---------------- helpers ----------------
__device__ __forceinline__ uint32_t smem_u32(const void* p) {
    uint32_t a;
    asm("{ .reg .u64 t; cvta.to.shared.u64 t, %1; cvt.u32.u64 %0, t; }" : "=r"(a) : "l"(p));
    return a;
}
__device__ __forceinline__ uint32_t pack2bf(float lo, float hi) {
    uint32_t r;
    asm("cvt.rn.bf16x2.f32 %0, %1, %2;" : "=r"(r) : "f"(hi), "f"(lo));
    return r;
}
__device__ __forceinline__ void split2(float x, float y, uint32_t& hi, uint32_t& lo) {
    hi = pack2bf(x, y);
    __nv_bfloat162 h2 = *reinterpret_cast<__nv_bfloat162*>(&hi);
    lo = pack2bf(x - __bfloat162float(h2.x), y - __bfloat162float(h2.y));
}
__device__ __forceinline__ void ldsm4(uint32_t* r, uint32_t addr) {
    asm volatile("ldmatrix.sync.aligned.m8n8.x4.shared.b16 {%0,%1,%2,%3}, [%4];"
        : "=r"(r[0]), "=r"(r[1]), "=r"(r[2]), "=r"(r[3]) : "r"(addr));
}
__device__ __forceinline__ void mma_bf16(float* c, const uint32_t* a, const uint32_t* b) {
    asm volatile("mma.sync.aligned.m16n8k16.row.col.f32.bf16.bf16.f32 "
        "{%0,%1,%2,%3}, {%4,%5,%6,%7}, {%8,%9}, {%0,%1,%2,%3};"
        : "+f"(c[0]), "+f"(c[1]), "+f"(c[2]), "+f"(c[3])
        : "r"(a[0]), "r"(a[1]), "r"(a[2]), "r"(a[3]), "r"(b[0]), "r"(b[1]));
}

// ---------------- weight transpose + bf16 split: W[k][n] -> WT_hi/lo[n][k] ----------------
__global__ void transpose_conv(const float* __restrict__ W0, const float* __restrict__ W1,
                               const float* __restrict__ W2, const float* __restrict__ W3)
{
    __shared__ float t[32][33];
    const float* W = (blockIdx.z == 0) ? W0 : (blockIdx.z == 1) ? W1 : (blockIdx.z == 2) ? W2 : W3;
    __nv_bfloat16* oh = g_WTh[blockIdx.z];
    __nv_bfloat16* ol = g_WTl[blockIdx.z];
    const int k0 = blockIdx.y * 32, n0 = blockIdx.x * 32;
    const int tx = threadIdx.x, ty = threadIdx.y;
#pragma unroll
    for (int i = 0; i < 32; i += 8)
        t[ty + i][tx] = W[(size_t)(k0 + ty + i) * Dc + n0 + tx];
    __syncthreads();
#pragma unroll
    for (int i = 0; i < 32; i += 8) {
        float v = t[tx][ty + i];
        __nv_bfloat16 h = __float2bfloat16(v);
        __nv_bfloat16 l = __float2bfloat16(v - __bfloat162float(h));
        size_t o = (size_t)(n0 + ty + i) * Dc + k0 + tx;
        oh[o] = h; ol[o] = l;
    }
}

// ---------------- fp32 -> bf16 hi/lo (row-major) into g_Ah/g_Al ----------------
__global__ void conv_split(const float* __restrict__ X)
{
    size_t e = (size_t)blockIdx.x * 256 + threadIdx.x;  // float4 index
    float4 v = *(const float4*)(X + e * 4);
    uint32_t h0, l0, h1, l1;
    split2(v.x, v.y, h0, l0);
    split2(v.z, v.w, h1, l1);
    *(uint2*)(g_Ah + e * 4) = make_uint2(h0, h1);
    *(uint2*)(g_Al + e * 4) = make_uint2(l0, l1);
}

// ===========================================================================
// mma_gemm: C[128x128] = A[4096x1024] @ WT[widx]^T with bf16x3 compensation.
// mode 0: -> Qh/Ql head layout   mode 1: -> Kh/Kl head layout
// mode 2: -> VTh/VTl [bh][dk][s] mode 3: A=g_att, -> g_fc (+bias+resid)
// ===========================================================================
#define GRS 80                  // smem row stride bytes (32 bf16 + pad 8)
#define GBUF 40960              // 4 matrices x 128 x 80B
#define SM_G (2*GBUF)           // 81920; stage (128*132*4=67584) reuses it
#define STG 132                 // stage stride (floats), multiple of 4

__global__ __launch_bounds__(256, 1) void mma_gemm(int widx, int mode,
                                                   const float* __restrict__ bias,
                                                   const float* __restrict__ resid)
{
    extern __shared__ __align__(16) char smem[];
    const uint32_t sb = smem_u32(smem);

    const int tid  = threadIdx.x;
    const int lane = tid & 31;
    const int wid  = tid >> 5;
    const int wm   = wid >> 2;          // 0..1  (m warp)
    const int wn   = wid & 3;           // 0..3  (n warp)
    const int m0 = blockIdx.y * 128;
    const int n0 = blockIdx.x * 128;

    const __nv_bfloat16* Ah = (mode == 3) ? g_atth : g_Ah;
    const __nv_bfloat16* Al = (mode == 3) ? g_attl : g_Al;
    const __nv_bfloat16* Bh = g_WTh[widx];
    const __nv_bfloat16* Bl = g_WTl[widx];

    // per-thread global load mapping (same for A and B tiles: 128 rows x 32 k)
    const int e0 = tid, e1 = tid + 256;
    const int r0 = e0 >> 2, c0 = (e0 & 3) * 8;
    const int r1 = e1 >> 2, c1 = (e1 & 3) * 8;
    const size_t ga0 = (size_t)(m0 + r0) * 1024 + c0;
    const size_t ga1 = (size_t)(m0 + r1) * 1024 + c1;
    const size_t gb0 = (size_t)(n0 + r0) * 1024 + c0;
    const size_t gb1 = (size_t)(n0 + r1) * 1024 + c1;
    const uint32_t s0 = r0 * GRS + c0 * 2;
    const uint32_t s1 = r1 * GRS + c1 * 2;

    // ldmatrix per-thread offsets
    const int arow = lane & 15;
    const int acol = (lane & 16) ? 8 : 0;
    const int brow = ((lane & 16) >> 1) + (lane & 7);
    const int bcol = (lane & 8);

    float acc[4][4][4];
#pragma unroll
    for (int i = 0; i < 4; i++)
#pragma unroll
        for (int j = 0; j < 4; j++)
#pragma unroll
            for (int q = 0; q < 4; q++) acc[i][j][q] = 0.0f;

    uint4 rah, ral, rbh_, rbl_, rah1, ral1, rbh1, rbl1;

    // prologue: chunk 0
    {
        rah  = *(const uint4*)(Ah + ga0); rah1 = *(const uint4*)(Ah + ga1);
        ral  = *(const uint4*)(Al + ga0); ral1 = *(const uint4*)(Al + ga1);
        rbh_ = *(const uint4*)(Bh + gb0); rbh1 = *(const uint4*)(Bh + gb1);
        rbl_ = *(const uint4*)(Bl + gb0); rbl1 = *(const uint4*)(Bl + gb1);
        char* b = smem;
        *(uint4*)(b + 0*10240 + s0) = rah;  *(uint4*)(b + 0*10240 + s1) = rah1;
        *(uint4*)(b + 1*10240 + s0) = ral;  *(uint4*)(b + 1*10240 + s1) = ral1;
        *(uint4*)(b + 2*10240 + s0) = rbh_; *(uint4*)(b + 2*10240 + s1) = rbh1;
        *(uint4*)(b + 3*10240 + s0) = rbl_; *(uint4*)(b + 3*10240 + s1) = rbl1;
    }
    __syncthreads();

    for (int c = 0; c < 32; c++) {
        if (c < 31) {
            const int k = (c + 1) * 32;
            rah  = *(const uint4*)(Ah + ga0 + k); rah1 = *(const uint4*)(Ah + ga1 + k);
            ral  = *(const uint4*)(Al + ga0 + k); ral1 = *(const uint4*)(Al + ga1 + k);
            rbh_ = *(const uint4*)(Bh + gb0 + k); rbh1 = *(const uint4*)(Bh + gb1 + k);
            rbl_ = *(const uint4*)(Bl + gb0 + k); rbl1 = *(const uint4*)(Bl + gb1 + k);
        }
        const uint32_t bb = sb + (c & 1) * GBUF;
        const uint32_t aH = bb, aL = bb + 10240, bH = bb + 20480, bL = bb + 30720;
#pragma unroll
        for (int ks = 0; ks < 2; ks++) {
            const int k0s = ks * 16;
            uint32_t afh[4][4], afl[4][4], bfh[2][4], bfl[2][4];
#pragma unroll
            for (int mi = 0; mi < 4; mi++) {
                const uint32_t off = (uint32_t)(wm*64 + mi*16 + arow) * GRS + (k0s + acol) * 2;
                ldsm4(afh[mi], aH + off);
                ldsm4(afl[mi], aL + off);
            }
#pragma unroll
            for (int j = 0; j < 2; j++) {
                const uint32_t off = (uint32_t)(wn*32 + j*16 + brow) * GRS + (k0s + bcol) * 2;
                ldsm4(bfh[j], bH + off);
                ldsm4(bfl[j], bL + off);
            }
#pragma unroll
            for (int mi = 0; mi < 4; mi++)
#pragma unroll
                for (int ni = 0; ni < 4; ni++) {
                    const uint32_t* ph = &bfh[ni >> 1][(ni & 1) * 2];
                    const uint32_t* pl = &bfl[ni >> 1][(ni & 1) * 2];
                    mma_bf16(acc[mi][ni], afh[mi], ph);
                    mma_bf16(acc[mi][ni], afh[mi], pl);
                    mma_bf16(acc[mi][ni], afl[mi], ph);
                }
        }
        if (c < 31) {
            char* b = smem + ((c + 1) & 1) * GBUF;
            *(uint4*)(b + 0*10240 + s0) = rah;  *(uint4*)(b + 0*10240 + s1) = rah1;
            *(uint4*)(b + 1*10240 + s0) = ral;  *(uint4*)(b + 1*10240 + s1) = ral1;
            *(uint4*)(b + 2*10240 + s0) = rbh_; *(uint4*)(b + 2*10240 + s1) = rbh1;
            *(uint4*)(b + 3*10240 + s0) = rbl_; *(uint4*)(b + 3*10240 + s1) = rbl1;
        }
        __syncthreads();
    }

    // accumulators -> smem stage (stride 132 floats, 16B aligned)
    float* stage = (float*)smem;
#pragma unroll
    for (int mi = 0; mi < 4; mi++)
#pragma unroll
        for (int ni = 0; ni < 4; ni++) {
            const int row = wm*64 + mi*16 + (lane >> 2);
            const int col = wn*32 + ni*8 + (lane & 3) * 2;
            *(float2*)&stage[row * STG + col]       = make_float2(acc[mi][ni][0], acc[mi][ni][1]);
            *(float2*)&stage[(row + 8) * STG + col] = make_float2(acc[mi][ni][2], acc[mi][ni][3]);
        }
    __syncthreads();

    if (mode <= 1) {
        __nv_bfloat16* oh = (mode == 0) ? g_Qh : g_Kh;
        __nv_bfloat16* ol = (mode == 0) ? g_Ql : g_Kl;
#pragma unroll
        for (int i = 0; i < 16; i++) {
            const int e = tid + i * 256;
            const int r = e >> 5, c4 = (e & 31) * 4;
            float4 v = *(const float4*)&stage[r * STG + c4];
            const int m = m0 + r, b = m >> 10, s = m & 1023;
            const int n = n0 + c4, h = n >> 6, dk = n & 63;
            uint32_t h0, l0, h1, l1;
            split2(v.x, v.y, h0, l0);
            split2(v.z, v.w, h1, l1);
            const size_t dst = ((size_t)(b * 16 + h) * 1024 + s) * 64 + dk;
            *(uint2*)(oh + dst) = make_uint2(h0, h1);
            *(uint2*)(ol + dst) = make_uint2(l0, l1);
        }
    } else if (mode == 2) {
        const int r = tid & 127, half = tid >> 7;
        const int b = m0 >> 10, s0r = m0 & 1023;
#pragma unroll 8
        for (int j = 0; j < 64; j++) {
            const int c = half * 64 + j;
            const float v = stage[r * STG + c];
            __nv_bfloat16 hv = __float2bfloat16(v);
            __nv_bfloat16 lv = __float2bfloat16(v - __bfloat162float(hv));
            const int n = n0 + c, hh = n >> 6, dk = n & 63;
            const size_t dst = ((size_t)(b * 16 + hh) * 64 + dk) * 1024 + s0r + r;
            g_VTh[dst] = hv; g_VTl[dst] = lv;
        }
    } else {
#pragma unroll
        for (int i = 0; i < 16; i++) {
            const int e = tid + i * 256;
            const int r = e >> 5, c4 = (e & 31) * 4;
            float4 v = *(const float4*)&stage[r * STG + c4];
            const int m = m0 + r, n = n0 + c4;
            float4 bi = *(const float4*)(bias + n);
            float4 rs = *(const float4*)(resid + (size_t)m * 1024 + n);
            v.x += bi.x + rs.x; v.y += bi.y + rs.y;
            v.z += bi.z + rs.z; v.w += bi.w + rs.w;
            *(float4*)(g_fc + (size_t)m * 1024 + n) = v;
        }
    }
}

// ===========================================================================
// scores: p_raw[bh][q][n] = QK^T/8 + rel, mask -> -1e9. mma bf16x3, K=64.
// CTA 128q x 128n. Grid (8, 8, 64).
// ===========================================================================
#define SRS 144                 // 64 bf16 + pad 8 -> 144 bytes
#define SM_S (4*128*SRS)        // 73728; fp32 stage (67584) reuses it

__global__ __launch_bounds__(256, 1) void scores_mma(const float* __restrict__ rel,
                                                     const int*   __restrict__ mask,
                                                     float* __restrict__ p)
{
    extern __shared__ __align__(16) char smem[];
    const uint32_t sb = smem_u32(smem);
    const uint32_t qH = sb, qL = sb + 18432, kH = sb + 36864, kL = sb + 55296;

    const int tid = threadIdx.x, lane = tid & 31, wid = tid >> 5;
    const int wm = wid >> 2, wn = wid & 3;
    const int bh = blockIdx.z, q0 = blockIdx.y * 128, n0 = blockIdx.x * 128;
    const size_t base = (size_t)bh * Sc * DKc;

    // load Q/K tiles (hi/lo): 128 rows x 64 k each
#pragma unroll
    for (int i = 0; i < 4; i++) {
        const int e = tid + i * 256;
        const int r = e >> 3, c8 = (e & 7) * 8;
        const uint32_t so = (uint32_t)r * SRS + c8 * 2;
        *(uint4*)(smem + 0     + so) = *(const uint4*)(g_Qh + base + (size_t)(q0 + r) * 64 + c8);
        *(uint4*)(smem + 18432 + so) = *(const uint4*)(g_Ql + base + (size_t)(q0 + r) * 64 + c8);
        *(uint4*)(smem + 36864 + so) = *(const uint4*)(g_Kh + base + (size_t)(n0 + r) * 64 + c8);
        *(uint4*)(smem + 55296 + so) = *(const uint4*)(g_Kl + base + (size_t)(n0 + r) * 64 + c8);
    }
    __syncthreads();

    const int arow = lane & 15;
    const int acol = (lane & 16) ? 8 : 0;
    const int brow = ((lane & 16) >> 1) + (lane & 7);
    const int bcol = (lane & 8);

    float acc[4][4][4];
#pragma unroll
    for (int i = 0; i < 4; i++)
#pragma unroll
        for (int j = 0; j < 4; j++)
#pragma unroll
            for (int q = 0; q < 4; q++) acc[i][j][q] = 0.0f;

#pragma unroll
    for (int ks = 0; ks < 4; ks++) {
        const int k0s = ks * 16;
        uint32_t afh[4][4], afl[4][4], bfh[2][4], bfl[2][4];
#pragma unroll
        for (int mi = 0; mi < 4; mi++) {
            const uint32_t off = (uint32_t)(wm*64 + mi*16 + arow) * SRS + (k0s + acol) * 2;
            ldsm4(afh[mi], qH + off);
            ldsm4(afl[mi], qL + off);
        }
#pragma unroll
        for (int j = 0; j < 2; j++) {
            const uint32_t off = (uint32_t)(wn*32 + j*16 + brow) * SRS + (k0s + bcol) * 2;
            ldsm4(bfh[j], kH + off);
            ldsm4(bfl[j], kL + off);
        }
#pragma unroll
        for (int mi = 0; mi < 4; mi++)
#pragma unroll
            for (int ni = 0; ni < 4; ni++) {
                const uint32_t* ph = &bfh[ni >> 1][(ni & 1) * 2];
                const uint32_t* pl = &bfl[ni >> 1][(ni & 1) * 2];
                mma_bf16(acc[mi][ni], afh[mi], ph);
                mma_bf16(acc[mi][ni], afh[mi], pl);
                mma_bf16(acc[mi][ni], afl[mi], ph);
            }
    }
    __syncthreads();

    float* stage = (float*)smem;
#pragma unroll
    for (int mi = 0; mi < 4; mi++)
#pragma unroll
        for (int ni = 0; ni < 4; ni++) {
            const int row = wm*64 + mi*16 + (lane >> 2);
            const int col = wn*32 + ni*8 + (lane & 3) * 2;
            *(float2*)&stage[row * STG + col]       = make_float2(acc[mi][ni][0], acc[mi][ni][1]);
            *(float2*)&stage[(row + 8) * STG + col] = make_float2(acc[mi][ni][2], acc[mi][ni][3]);
        }
    __syncthreads();

    const int b = bh >> 4;
#pragma unroll
    for (int i = 0; i < 16; i++) {
        const int e = tid + i * 256;
        const int r = e >> 5, c4 = (e & 31) * 4;
        const int q = q0 + r, n = n0 + c4;
        float4 v = *(const float4*)&stage[r * STG + c4];
        const size_t ridx = ((size_t)b * Sc + q) * Sc + n;
        float4 r4 = *(const float4*)(rel + ridx);
        int4   m4 = *(const int4*)(mask + ridx);
        float4 o;
        o.x = m4.x ? -1e9f : fmaf(v.x, 0.125f, r4.x);
        o.y = m4.y ? -1e9f : fmaf(v.y, 0.125f, r4.y);
        o.z = m4.z ? -1e9f : fmaf(v.z, 0.125f, r4.z);
        o.w = m4.w ? -1e9f : fmaf(v.w, 0.125f, r4.w);
        *(float4*)(p + ((size_t)bh * Sc + q) * Sc + n) = o;
    }
}

// ---------------- softmax (in-place, 1024-wide rows) ----------------
__global__ __launch_bounds__(256) void softmax_kernel(float* __restrict__ p)
{
    __shared__ float smax[8], ssum[8];
    float* pr = p + (size_t)blockIdx.x * 1024;
    const int tid = threadIdx.x, lane = tid & 31, w = tid >> 5;

    float4 v = *(float4*)(pr + tid * 4);
    float m = fmaxf(fmaxf(v.x, v.y), fmaxf(v.z, v.w));
#pragma unroll
    for (int o = 16; o > 0; o >>= 1) m = fmaxf(m, __shfl_xor_sync(0xffffffffu, m, o));
    if (lane == 0) smax[w] = m;
    __syncthreads();
    m = smax[0];
#pragma unroll
    for (int i = 1; i < 8; i++) m = fmaxf(m, smax[i]);

    v.x = expf(v.x - m); v.y = expf(v.y - m);
    v.z = expf(v.z - m); v.w = expf(v.w - m);
    float s = v.x + v.y + v.z + v.w;
#pragma unroll
    for (int o = 16; o > 0; o >>= 1) s += __shfl_xor_sync(0xffffffffu, s, o);
    if (lane == 0) ssum[w] = s;
    __syncthreads();
    s = ssum[0];
#pragma unroll
    for (int i = 1; i < 8; i++) s += ssum[i];

    const float inv = 1.0f / s;
    v.x *= inv; v.y *= inv; v.z *= inv; v.w *= inv;
    *(float4*)(pr + tid * 4) = v;
}

// ===========================================================================
// att: att[q][dk] = P @ V via mma. P fp32 split on the fly; V pre-split (VT).
// CTA 128q x 64dk, k-chunks of 32. Grid (8, 64). Output -> g_atth/l [m][1024].
// ===========================================================================
#define ABUF 30720              // Ph(10240)+Pl(10240)+Vh(5120)+Vl(5120)
#define SM_A (2*ABUF)           // 61440; stage 128*68*4=34816 reuses it

__global__ __launch_bounds__(256, 1) void att_mma(const float* __restrict__ p)
{
    extern __shared__ __align__(16) char smem[];
    const uint32_t sb = smem_u32(smem);

    const int tid = threadIdx.x, lane = tid & 31, wid = tid >> 5;
    const int wm = wid >> 1, wn = wid & 1;
    const int q0 = blockIdx.x * 128, bh = blockIdx.y;
    const float* Pb = p + ((size_t)bh * 1024 + q0) * 1024;
    const __nv_bfloat16* Vh = g_VTh + (size_t)bh * 64 * 1024;
    const __nv_bfloat16* Vl = g_VTl + (size_t)bh * 64 * 1024;

    // P load mapping: 4 float4/thread
    int pr_[4], pc_[4];
#pragma unroll
    for (int i = 0; i < 4; i++) {
        const int e = tid + i * 256;
        pr_[i] = e >> 3; pc_[i] = (e & 7) * 4;
    }
    const int vr = tid >> 2, vc = (tid & 3) * 8;

    const int arow = lane & 15;
    const int acol = (lane & 16) ? 8 : 0;
    const int brow = ((lane & 16) >> 1) + (lane & 7);
    const int bcol = (lane & 8);

    float acc[2][4][4];
#pragma unroll
    for (int i = 0; i < 2; i++)
#pragma unroll
        for (int j = 0; j < 4; j++)
#pragma unroll
            for (int q = 0; q < 4; q++) acc[i][j][q] = 0.0f;

    float4 pv[4]; uint4 vvh, vvl;
    // prologue chunk 0
#pragma unroll
    for (int i = 0; i < 4; i++) pv[i] = *(const float4*)(Pb + (size_t)pr_[i] * 1024 + pc_[i]);
    vvh = *(const uint4*)(Vh + (size_t)vr * 1024 + vc);
    vvl = *(const uint4*)(Vl + (size_t)vr * 1024 + vc);
    {
        char* b = smem;
#pragma unroll
        for (int i = 0; i < 4; i++) {
            uint32_t h0, l0, h1, l1;
            split2(pv[i].x, pv[i].y, h0, l0);
            split2(pv[i].z, pv[i].w, h1, l1);
            const uint32_t so = (uint32_t)pr_[i] * 80 + pc_[i] * 2;
            *(uint2*)(b + so)         = make_uint2(h0, h1);
            *(uint2*)(b + 10240 + so) = make_uint2(l0, l1);
        }
        const uint32_t so = (uint32_t)vr * 80 + vc * 2;
        *(uint4*)(b + 20480 + so) = vvh;
        *(uint4*)(b + 25600 + so) = vvl;
    }
    __syncthreads();

    for (int c = 0; c < 32; c++) {
        if (c < 31) {
            const int k = (c + 1) * 32;
#pragma unroll
            for (int i = 0; i < 4; i++) pv[i] = *(const float4*)(Pb + (size_t)pr_[i] * 1024 + k + pc_[i]);
            vvh = *(const uint4*)(Vh + (size_t)vr * 1024 + k + vc);
            vvl = *(const uint4*)(Vl + (size_t)vr * 1024 + k + vc);
        }
        const uint32_t bb = sb + (c & 1) * ABUF;
        const uint32_t pH = bb, pL = bb + 10240, vH = bb + 20480, vL = bb + 25600;
#pragma unroll
        for (int ks = 0; ks < 2; ks++) {
            const int k0s = ks * 16;
            uint32_t afh[2][4], afl[2][4], bfh[2][4], bfl[2][4];
#pragma unroll
            for (int mi = 0; mi < 2; mi++) {
                const uint32_t off = (uint32_t)(wm*32 + mi*16 + arow) * 80 + (k0s + acol) * 2;
                ldsm4(afh[mi], pH + off);
                ldsm4(afl[mi], pL + off);
            }
#pragma unroll
            for (int j = 0; j < 2; j++) {
                const uint32_t off = (uint32_t)(wn*32 + j*16 + brow) * 80 + (k0s + bcol) * 2;
                ldsm4(bfh[j], vH + off);
                ldsm4(bfl[j], vL + off);
            }
#pragma unroll
            for (int mi = 0; mi < 2; mi++)
#pragma unroll
                for (int ni = 0; ni < 4; ni++) {
                    const uint32_t* ph = &bfh[ni >> 1][(ni & 1) * 2];
                    const uint32_t* pl = &bfl[ni >> 1][(ni & 1) * 2];
                    mma_bf16(acc[mi][ni], afh[mi], ph);
                    mma_bf16(acc[mi][ni], afh[mi], pl);
                    mma_bf16(acc[mi][ni], afl[mi], ph);
                }
        }
        if (c < 31) {
            char* b = smem + ((c + 1) & 1) * ABUF;
#pragma unroll
            for (int i = 0; i < 4; i++) {
                uint32_t h0, l0, h1, l1;
                split2(pv[i].x, pv[i].y, h0, l0);
                split2(pv[i].z, pv[i].w, h1, l1);
                const uint32_t so = (uint32_t)pr_[i] * 80 + pc_[i] * 2;
                *(uint2*)(b + so)         = make_uint2(h0, h1);
                *(uint2*)(b + 10240 + so) = make_uint2(l0, l1);
            }
            const uint32_t so = (uint32_t)vr * 80 + vc * 2;
            *(uint4*)(b + 20480 + so) = vvh;
            *(uint4*)(b + 25600 + so) = vvl;
        }
        __syncthreads();
    }

    float* stage = (float*)smem;   // [128][68]
#pragma unroll
    for (int mi = 0; mi < 2; mi++)
#pragma unroll
        for (int ni = 0; ni < 4; ni++) {
            const int row = wm*32 + mi*16 + (lane >> 2);
            const int col = wn*32 + ni*8 + (lane & 3) * 2;
            *(float2*)&stage[row * 68 + col]       = make_float2(acc[mi][ni][0], acc[mi][ni][1]);
            *(float2*)&stage[(row + 8) * 68 + col] = make_float2(acc[mi][ni][2], acc[mi][ni][3]);
        }
    __syncthreads();

    const int b = bh >> 4, h = bh & 15;
#pragma unroll
    for (int i = 0; i < 8; i++) {
        const int e = tid + i * 256;
        const int r = e >> 4, c4 = (e & 15) * 4;
        float4 v = *(const float4*)&stage[r * 68 + c4];
        uint32_t h0, l0, h1, l1;
        split2(v.x, v.y, h0, l0);
        split2(v.z, v.w, h1, l1);
        const size_t dst = ((size_t)(b * 1024) + q0 + r) * 1024 + h * 64 + c4;
        *(uint2*)(g_atth + dst) = make_uint2(h0, h1);
        *(uint2*)(g_attl + dst) = make_uint2(l0, l1);
    }
}

// ---------------- LayerNorm ----------------
__global__ __launch_bounds__(256) void ln_kernel(const float* __restrict__ g,
                                                 const float* __restrict__ bta,
                                                 float* __restrict__ y)
{
    __shared__ float s1[8], s2[8];
    const int row = blockIdx.x, tid = threadIdx.x, lane = tid & 31, w = tid >> 5;
    const float* xr = g_fc + (size_t)row * 1024;

    float4 v = *(const float4*)(xr + tid * 4);
    float s = v.x + v.y + v.z + v.w;
    float q = v.x*v.x + v.y*v.y + v.z*v.z + v.w*v.w;
#pragma unroll
    for (int o = 16; o > 0; o >>= 1) {
        s += __shfl_xor_sync(0xffffffffu, s, o);
        q += __shfl_xor_sync(0xffffffffu, q, o);
    }
    if (lane == 0) { s1[w] = s; s2[w] = q; }
    __syncthreads();
    s = 0.0f; q = 0.0f;
#pragma unroll
    for (int i = 0; i < 8; i++) { s += s1[i]; q += s2[i]; }

    const float mu  = s * (1.0f / 1024.0f);
    const float var = q * (1.0f / 1024.0f) - mu * mu;
    const float rs  = rsqrtf(var + 1e-5f);

    float4 gg = *(const float4*)(g   + tid * 4);
    float4 bb = *(const float4*)(bta + tid * 4);
    float4 o;
    o.x = (v.x - mu) * rs * gg.x + bb.x;
    o.y = (v.y - mu) * rs * gg.y + bb.y;
    o.z = (v.z - mu) * rs * gg.z + bb.z;
    o.w = (v.w - mu) * rs * gg.w + bb.w;
    *(float4*)(y + (size_t)row * 1024 + tid * 4) = o;
}

// ---------------------------------------------------------------------------
extern "C" void kernel_launch(void* const* d_in, const int* in_sizes, int n_in,
                              void* d_out, int out_size)
{
    const float* query    = (const float*)d_in[0];
    const float* key      = (const float*)d_in[1];
    const float* value    = (const float*)d_in[2];
    const int*   mask     = (const int*)  d_in[3];
    const float* relation = (const float*)d_in[4];
    const float* Wq       = (const float*)d_in[5];
    const float* Wk       = (const float*)d_in[6];
    const float* Wv       = (const float*)d_in[7];
    const float* fc_w     = (const float*)d_in[8];
    const float* fc_b     = (const float*)d_in[9];
    const float* ln_g     = (const float*)d_in[10];
    const float* ln_b     = (const float*)d_in[11];

    float* y = (float*)d_out;
    float* p = y + (size_t)YSIZE;

    static bool attr_set = false;
    if (!attr_set) {
        cudaFuncSetAttribute(mma_gemm,   cudaFuncAttributeMaxDynamicSharedMemorySize, SM_G);
        cudaFuncSetAttribute(scores_mma, cudaFuncAttributeMaxDynamicSharedMemorySize, SM_S);
        cudaFuncSetAttribute(att_mma,    cudaFuncAttributeMaxDynamicSharedMemorySize, SM_A);
        attr_set = true;
    }

    transpose_conv<<<dim3(32, 32, 4), dim3(32, 8)>>>(Wq, Wk, Wv, fc_w);

    dim3 gg(8, 32);
    conv_split<<<4096, 256>>>(query);
    mma_gemm<<<gg, 256, SM_G>>>(0, 0, nullptr, nullptr);
    conv_split<<<4096, 256>>>(key);
    mma_gemm<<<gg, 256, SM_G>>>(1, 1, nullptr, nullptr);
    conv_split<<<4096, 256>>>(value);
    mma_gemm<<<gg, 256, SM_G>>>(2, 2, nullptr, nullptr);

    scores_mma<<<dim3(8, 8, 64), 256, SM_S>>>(relation, mask, p);
    softmax_kernel<<<BHc * Sc, 256>>>(p);
    att_mma<<<dim3(8, 64), 256, SM_A>>>(p);

    mma_gemm<<<gg, 256, SM_G>>>(3, 3, fc_b, query);
    ln_kernel<<<Mc, 256>>>(ln_g, ln_b, y);
}

// round 6
// speedup vs baseline: 2.4544x; 1.1682x over previous
#include <cuda_runtime.h>
#include <math.h>
#include <stdint.h>

#define Bc   4
#define Sc   1024
#define Dc   1024
#define Hc   16
#define DKc  64
#define Mc   (Bc*Sc)        // 4096
#define BHc  (Bc*Hc)        // 64
#define YSIZE (Bc*Sc*Dc)

// ---------------- device scratch ----------------
__device__ float g_Q[Mc*Dc];        // [bh][s][dk]
__device__ float g_K[Mc*Dc];        // [bh][s][dk]
__device__ float g_VT[Mc*Dc];       // [bh][dk][s]
__device__ float g_att[Mc*Dc];      // [m][h*dk]
__device__ float g_fc[Mc*Dc];       // fc + resid
__device__ float g_WT[4][Dc*Dc];    // WT[n][k]
__device__ float g_pmax[BHc*8*Sc];  // [bh][nt][q]
__device__ float g_psum[BHc*8*Sc];
__device__ float g_scale[BHc*8*Sc];

// ---------------- helpers ----------------
__device__ __forceinline__ float tf32r(float x) {
    uint32_t u;
    asm("cvt.rna.tf32.f32 %0, %1;" : "=r"(u) : "f"(x));
    return __uint_as_float(u);
}
__device__ __forceinline__ void mma_tf32(float* c, const float* a, const float* b) {
    asm volatile("mma.sync.aligned.m16n8k8.row.col.f32.tf32.tf32.f32 "
        "{%0,%1,%2,%3}, {%4,%5,%6,%7}, {%8,%9}, {%0,%1,%2,%3};"
        : "+f"(c[0]), "+f"(c[1]), "+f"(c[2]), "+f"(c[3])
        : "r"(__float_as_uint(a[0])), "r"(__float_as_uint(a[1])),
          "r"(__float_as_uint(a[2])), "r"(__float_as_uint(a[3])),
          "r"(__float_as_uint(b[0])), "r"(__float_as_uint(b[1])));
}
__device__ __forceinline__ void st4cvt(float* d, float4 v) {
    float4 o = make_float4(tf32r(v.x), tf32r(v.y), tf32r(v.z), tf32r(v.w));
    *(float4*)d = o;
}

// ---------------- weight transpose: W[k][n] -> WT[n][k] ----------------
__global__ void transpose_w(const float* __restrict__ W, int widx)
{
    __shared__ float t[32][33];
    float* o = g_WT[widx];
    const int k0 = blockIdx.y * 32, n0 = blockIdx.x * 32;
    const int tx = threadIdx.x, ty = threadIdx.y;   // 32 x 8
#pragma unroll
    for (int i = 0; i < 32; i += 8)
        t[ty + i][tx] = W[(size_t)(k0 + ty + i) * Dc + n0 + tx];
    __syncthreads();
#pragma unroll
    for (int i = 0; i < 32; i += 8)
        o[(size_t)(n0 + ty + i) * Dc + k0 + tx] = t[tx][ty + i];
}

// ===========================================================================
// tf32 GEMM: C[128x128] = A[4096x1024] @ WT^T.
// mode 0: -> g_Q head layout   mode 1: -> g_K head layout
// mode 2: -> g_VT [bh][dk][s]  mode 3: A=g_att, -> g_fc (+bias+resid)
// ===========================================================================
#define GST 36
#define GTILE (128*GST*4)          // 18432 bytes
#define GBUF  (2*GTILE)            // 36864
#define SM_G  (2*GBUF)             // 73728
#define STG 132

__global__ __launch_bounds__(256, 1) void mma_gemm(const float* __restrict__ Ain,
                                                   int widx, int mode,
                                                   const float* __restrict__ bias,
                                                   const float* __restrict__ resid)
{
    extern __shared__ __align__(16) char smem[];
    const int tid  = threadIdx.x;
    const int lane = tid & 31;
    const int wid  = tid >> 5;
    const int wm   = wid >> 2;          // 0..1
    const int wn   = wid & 3;           // 0..3
    const int g    = lane >> 2;
    const int cc   = lane & 3;
    const int m0 = blockIdx.y * 128;
    const int n0 = blockIdx.x * 128;

    const float* A = (mode == 3) ? g_att : Ain;
    const float* B = g_WT[widx];

    const int fr = tid >> 3, fc = (tid & 7) * 4;
    const size_t gA = (size_t)(m0 + fr) * 1024 + fc;
    const size_t gB = (size_t)(n0 + fr) * 1024 + fc;
    const uint32_t sOff = fr * GST + fc;

    float acc[4][4][4];
#pragma unroll
    for (int i = 0; i < 4; i++)
#pragma unroll
        for (int j = 0; j < 4; j++)
#pragma unroll
            for (int q = 0; q < 4; q++) acc[i][j][q] = 0.0f;

    float4 pa[4], pb[4];
#pragma unroll
    for (int j = 0; j < 4; j++) {
        pa[j] = *(const float4*)(A + gA + (size_t)j * 32 * 1024);
        pb[j] = *(const float4*)(B + gB + (size_t)j * 32 * 1024);
    }
    {
        float* As = (float*)smem;
        float* Bs = As + GTILE / 4;
#pragma unroll
        for (int j = 0; j < 4; j++) {
            st4cvt(As + sOff + j * 32 * GST, pa[j]);
            st4cvt(Bs + sOff + j * 32 * GST, pb[j]);
        }
    }
    __syncthreads();

    for (int kt = 0; kt < 32; kt++) {
        if (kt < 31) {
            const size_t ko = (size_t)(kt + 1) * 32;
#pragma unroll
            for (int j = 0; j < 4; j++) {
                pa[j] = *(const float4*)(A + gA + ko + (size_t)j * 32 * 1024);
                pb[j] = *(const float4*)(B + gB + ko + (size_t)j * 32 * 1024);
            }
        }
        const float* As = (float*)(smem + (kt & 1) * GBUF);
        const float* Bs = As + GTILE / 4;
#pragma unroll
        for (int kk = 0; kk < 32; kk += 8) {
            float af[4][4], bf[4][2];
#pragma unroll
            for (int mi = 0; mi < 4; mi++) {
                const int row = wm * 64 + mi * 16 + g;
                af[mi][0] = As[row * GST + kk + cc];
                af[mi][1] = As[(row + 8) * GST + kk + cc];
                af[mi][2] = As[row * GST + kk + cc + 4];
                af[mi][3] = As[(row + 8) * GST + kk + cc + 4];
            }
#pragma unroll
            for (int ni = 0; ni < 4; ni++) {
                const int col = wn * 32 + ni * 8 + g;
                bf[ni][0] = Bs[col * GST + kk + cc];
                bf[ni][1] = Bs[col * GST + kk + cc + 4];
            }
#pragma unroll
            for (int mi = 0; mi < 4; mi++)
#pragma unroll
                for (int ni = 0; ni < 4; ni++)
                    mma_tf32(acc[mi][ni], af[mi], bf[ni]);
        }
        if (kt < 31) {
            float* As2 = (float*)(smem + ((kt + 1) & 1) * GBUF);
            float* Bs2 = As2 + GTILE / 4;
#pragma unroll
            for (int j = 0; j < 4; j++) {
                st4cvt(As2 + sOff + j * 32 * GST, pa[j]);
                st4cvt(Bs2 + sOff + j * 32 * GST, pb[j]);
            }
        }
        __syncthreads();
    }

    float* stage = (float*)smem;
#pragma unroll
    for (int mi = 0; mi < 4; mi++)
#pragma unroll
        for (int ni = 0; ni < 4; ni++) {
            const int row = wm * 64 + mi * 16 + (lane >> 2);
            const int col = wn * 32 + ni * 8 + (lane & 3) * 2;
            *(float2*)&stage[row * STG + col]       = make_float2(acc[mi][ni][0], acc[mi][ni][1]);
            *(float2*)&stage[(row + 8) * STG + col] = make_float2(acc[mi][ni][2], acc[mi][ni][3]);
        }
    __syncthreads();

    if (mode <= 1) {
        float* out = (mode == 0) ? g_Q : g_K;
#pragma unroll
        for (int i = 0; i < 16; i++) {
            const int e = tid + i * 256;
            const int r = e >> 5, c4 = (e & 31) * 4;
            float4 v = *(const float4*)&stage[r * STG + c4];
            const int m = m0 + r, b = m >> 10, s = m & 1023;
            const int n = n0 + c4, h = n >> 6, dk = n & 63;
            *(float4*)(out + (((size_t)(b * 16 + h) * 1024 + s) * 64 + dk)) = v;
        }
    } else if (mode == 2) {
        const int r = tid & 127, half = tid >> 7;
        const int b = m0 >> 10, s0r = m0 & 1023;
#pragma unroll 8
        for (int j = 0; j < 64; j++) {
            const int c = half * 64 + j;
            const float v = stage[r * STG + c];
            const int n = n0 + c, hh = n >> 6, dk = n & 63;
            g_VT[((size_t)(b * 16 + hh) * 64 + dk) * 1024 + s0r + r] = v;
        }
    } else {
#pragma unroll
        for (int i = 0; i < 16; i++) {
            const int e = tid + i * 256;
            const int r = e >> 5, c4 = (e & 31) * 4;
            float4 v = *(const float4*)&stage[r * STG + c4];
            const int m = m0 + r, n = n0 + c4;
            float4 bi = *(const float4*)(bias + n);
            float4 rs = *(const float4*)(resid + (size_t)m * 1024 + n);
            v.x += bi.x + rs.x; v.y += bi.y + rs.y;
            v.z += bi.z + rs.z; v.w += bi.w + rs.w;
            *(float4*)(g_fc + (size_t)m * 1024 + n) = v;
        }
    }
}

// ===========================================================================
// scores (tf32) + partial softmax: writes exp(x - tilemax) into p and
// per-(row, n-tile) max/sum partials. CTA 128q x 128n, K=64. Grid (8,8,64).
// ===========================================================================
#define SST 68
#define SM_S (2*128*SST*4)          // 69632

__global__ __launch_bounds__(256, 1) void scores_mma(const float* __restrict__ rel,
                                                     const int*   __restrict__ mask,
                                                     float* __restrict__ p)
{
    extern __shared__ __align__(16) char smem[];
    float* Qs = (float*)smem;                 // [128][68]
    float* Ks = Qs + 128 * SST;

    const int tid = threadIdx.x, lane = tid & 31, wid = tid >> 5;
    const int wm = wid >> 2, wn = wid & 3;
    const int g = lane >> 2, cc = lane & 3;
    const int bh = blockIdx.z, q0 = blockIdx.y * 128, n0 = blockIdx.x * 128;
    const size_t base = (size_t)bh * Sc * DKc;

    {
        const int fr = tid >> 4, fc = (tid & 15) * 4;
#pragma unroll
        for (int j = 0; j < 8; j++) {
            const int r = fr + j * 16;
            st4cvt(Qs + r * SST + fc, *(const float4*)(g_Q + base + (size_t)(q0 + r) * 64 + fc));
            st4cvt(Ks + r * SST + fc, *(const float4*)(g_K + base + (size_t)(n0 + r) * 64 + fc));
        }
    }
    __syncthreads();

    float acc[4][4][4];
#pragma unroll
    for (int i = 0; i < 4; i++)
#pragma unroll
        for (int j = 0; j < 4; j++)
#pragma unroll
            for (int q = 0; q < 4; q++) acc[i][j][q] = 0.0f;

#pragma unroll
    for (int kk = 0; kk < 64; kk += 8) {
        float af[4][4], bf[4][2];
#pragma unroll
        for (int mi = 0; mi < 4; mi++) {
            const int row = wm * 64 + mi * 16 + g;
            af[mi][0] = Qs[row * SST + kk + cc];
            af[mi][1] = Qs[(row + 8) * SST + kk + cc];
            af[mi][2] = Qs[row * SST + kk + cc + 4];
            af[mi][3] = Qs[(row + 8) * SST + kk + cc + 4];
        }
#pragma unroll
        for (int ni = 0; ni < 4; ni++) {
            const int col = wn * 32 + ni * 8 + g;
            bf[ni][0] = Ks[col * SST + kk + cc];
            bf[ni][1] = Ks[col * SST + kk + cc + 4];
        }
#pragma unroll
        for (int mi = 0; mi < 4; mi++)
#pragma unroll
            for (int ni = 0; ni < 4; ni++)
                mma_tf32(acc[mi][ni], af[mi], bf[ni]);
    }
    __syncthreads();

    float* stage = (float*)smem;
#pragma unroll
    for (int mi = 0; mi < 4; mi++)
#pragma unroll
        for (int ni = 0; ni < 4; ni++) {
            const int row = wm * 64 + mi * 16 + (lane >> 2);
            const int col = wn * 32 + ni * 8 + (lane & 3) * 2;
            *(float2*)&stage[row * STG + col]       = make_float2(acc[mi][ni][0], acc[mi][ni][1]);
            *(float2*)&stage[(row + 8) * STG + col] = make_float2(acc[mi][ni][2], acc[mi][ni][3]);
        }
    __syncthreads();

    // epilogue: warp wid handles rows i*8+wid for i in [0,16) -> all 128 rows
    const int b = bh >> 4;
#pragma unroll
    for (int i = 0; i < 16; i++) {
        const int r = i * 8 + wid;
        const int q = q0 + r;
        const int n = n0 + lane * 4;
        float4 v = *(const float4*)&stage[r * STG + lane * 4];
        const size_t ridx = ((size_t)b * Sc + q) * Sc + n;
        float4 r4 = *(const float4*)(rel + ridx);
        int4   m4 = *(const int4*)(mask + ridx);
        float4 x;
        x.x = m4.x ? -1e9f : fmaf(v.x, 0.125f, r4.x);
        x.y = m4.y ? -1e9f : fmaf(v.y, 0.125f, r4.y);
        x.z = m4.z ? -1e9f : fmaf(v.z, 0.125f, r4.z);
        x.w = m4.w ? -1e9f : fmaf(v.w, 0.125f, r4.w);
        float mx = fmaxf(fmaxf(x.x, x.y), fmaxf(x.z, x.w));
#pragma unroll
        for (int o = 16; o > 0; o >>= 1) mx = fmaxf(mx, __shfl_xor_sync(0xffffffffu, mx, o));
        float4 e;
        e.x = __expf(x.x - mx); e.y = __expf(x.y - mx);
        e.z = __expf(x.z - mx); e.w = __expf(x.w - mx);
        float s = e.x + e.y + e.z + e.w;
#pragma unroll
        for (int o = 16; o > 0; o >>= 1) s += __shfl_xor_sync(0xffffffffu, s, o);
        *(float4*)(p + ((size_t)bh * Sc + q) * Sc + n) = e;
        if (lane == 0) {
            g_pmax[((size_t)bh * 8 + blockIdx.x) * Sc + q] = mx;
            g_psum[((size_t)bh * 8 + blockIdx.x) * Sc + q] = s;
        }
    }
}

// ---------------- combine: per-row softmax scale per n-tile ----------------
__global__ __launch_bounds__(256) void combine_kernel()
{
    const int row = blockIdx.x * 256 + threadIdx.x;   // 0..65535
    const int bh = row >> 10, q = row & 1023;
    float pm[8], ps[8];
#pragma unroll
    for (int t = 0; t < 8; t++) {
        pm[t] = g_pmax[((size_t)bh * 8 + t) * Sc + q];
        ps[t] = g_psum[((size_t)bh * 8 + t) * Sc + q];
    }
    float rm = pm[0];
#pragma unroll
    for (int t = 1; t < 8; t++) rm = fmaxf(rm, pm[t]);
    float rs = 0.0f;
#pragma unroll
    for (int t = 0; t < 8; t++) rs += ps[t] * __expf(pm[t] - rm);
    const float inv = 1.0f / rs;
#pragma unroll
    for (int t = 0; t < 8; t++)
        g_scale[((size_t)bh * 8 + t) * Sc + q] = __expf(pm[t] - rm) * inv;
}

// ===========================================================================
// att (tf32): finalizes p in-place (scale) and computes att = P @ V.
// CTA 128q x 64dk, k-tiles of 32, double-buffered. Grid (8, 64).
// ===========================================================================
#define AST 36
#define AT_PB (128*AST*4)           // 18432
#define AT_VB (64*AST*4)            // 9216
#define AT_BUF (AT_PB+AT_VB)        // 27648
#define SM_A (2*AT_BUF + 1024)
#define ATG 68

__global__ __launch_bounds__(256, 1) void att_mma(float* __restrict__ p)
{
    extern __shared__ __align__(16) char smem[];
    float* sscale = (float*)(smem + 2 * AT_BUF);   // [2][128]

    const int tid = threadIdx.x, lane = tid & 31, wid = tid >> 5;
    const int wm = wid >> 1, wn = wid & 1;
    const int g = lane >> 2, cc = lane & 3;
    const int q0 = blockIdx.x * 128, bh = blockIdx.y;
    float* Pb = p + ((size_t)bh * 1024 + q0) * 1024;
    const float* Vb = g_VT + (size_t)bh * 64 * 1024;

    const int fr = tid >> 3, fc = (tid & 7) * 4;

    float acc[2][4][4];
#pragma unroll
    for (int i = 0; i < 2; i++)
#pragma unroll
        for (int j = 0; j < 4; j++)
#pragma unroll
            for (int q = 0; q < 4; q++) acc[i][j][q] = 0.0f;

    float4 pa[4], pv[2];

    if (tid < 128) sscale[tid] = g_scale[((size_t)bh * 8 + 0) * Sc + q0 + tid];
    __syncthreads();
#pragma unroll
    for (int j = 0; j < 4; j++) pa[j] = *(const float4*)(Pb + (size_t)(fr + 32 * j) * 1024 + fc);
#pragma unroll
    for (int j = 0; j < 2; j++) pv[j] = *(const float4*)(Vb + (size_t)(fr + 32 * j) * 1024 + fc);
    {
        float* Ps = (float*)smem;
        float* Vs = Ps + AT_PB / 4;
#pragma unroll
        for (int j = 0; j < 4; j++) {
            const float s = sscale[fr + 32 * j];
            float4 pf = make_float4(pa[j].x * s, pa[j].y * s, pa[j].z * s, pa[j].w * s);
            *(float4*)(Pb + (size_t)(fr + 32 * j) * 1024 + fc) = pf;   // final p
            st4cvt(Ps + (fr + 32 * j) * AST + fc, pf);
        }
#pragma unroll
        for (int j = 0; j < 2; j++)
            st4cvt(Vs + (fr + 32 * j) * AST + fc, pv[j]);
    }
    __syncthreads();

    for (int kt = 0; kt < 32; kt++) {
        const int ktn = kt + 1;
        if (kt < 31) {
            const size_t ko = (size_t)ktn * 32;
#pragma unroll
            for (int j = 0; j < 4; j++) pa[j] = *(const float4*)(Pb + (size_t)(fr + 32 * j) * 1024 + ko + fc);
#pragma unroll
            for (int j = 0; j < 2; j++) pv[j] = *(const float4*)(Vb + (size_t)(fr + 32 * j) * 1024 + ko + fc);
            if ((ktn & 3) == 0) {
                const int nt = ktn >> 2;
                if (tid < 128) sscale[(nt & 1) * 128 + tid] = g_scale[((size_t)bh * 8 + nt) * Sc + q0 + tid];
                __syncthreads();
            }
        }
        const float* Ps = (float*)(smem + (kt & 1) * AT_BUF);
        const float* Vs = Ps + AT_PB / 4;
#pragma unroll
        for (int kk = 0; kk < 32; kk += 8) {
            float af[2][4], bf[4][2];
#pragma unroll
            for (int mi = 0; mi < 2; mi++) {
                const int row = wm * 32 + mi * 16 + g;
                af[mi][0] = Ps[row * AST + kk + cc];
                af[mi][1] = Ps[(row + 8) * AST + kk + cc];
                af[mi][2] = Ps[row * AST + kk + cc + 4];
                af[mi][3] = Ps[(row + 8) * AST + kk + cc + 4];
            }
#pragma unroll
            for (int ni = 0; ni < 4; ni++) {
                const int col = wn * 32 + ni * 8 + g;
                bf[ni][0] = Vs[col * AST + kk + cc];
                bf[ni][1] = Vs[col * AST + kk + cc + 4];
            }
#pragma unroll
            for (int mi = 0; mi < 2; mi++)
#pragma unroll
                for (int ni = 0; ni < 4; ni++)
                    mma_tf32(acc[mi][ni], af[mi], bf[ni]);
        }
        if (kt < 31) {
            float* Ps2 = (float*)(smem + (ktn & 1) * AT_BUF);
            float* Vs2 = Ps2 + AT_PB / 4;
            const int nt = ktn >> 2;
            const float* sc = sscale + (nt & 1) * 128;
            const size_t ko = (size_t)ktn * 32;
#pragma unroll
            for (int j = 0; j < 4; j++) {
                const float s = sc[fr + 32 * j];
                float4 pf = make_float4(pa[j].x * s, pa[j].y * s, pa[j].z * s, pa[j].w * s);
                *(float4*)(Pb + (size_t)(fr + 32 * j) * 1024 + ko + fc) = pf;
                st4cvt(Ps2 + (fr + 32 * j) * AST + fc, pf);
            }
#pragma unroll
            for (int j = 0; j < 2; j++)
                st4cvt(Vs2 + (fr + 32 * j) * AST + fc, pv[j]);
        }
        __syncthreads();
    }

    float* stage = (float*)smem;   // [128][68]
#pragma unroll
    for (int mi = 0; mi < 2; mi++)
#pragma unroll
        for (int ni = 0; ni < 4; ni++) {
            const int row = wm * 32 + mi * 16 + (lane >> 2);
            const int col = wn * 32 + ni * 8 + (lane & 3) * 2;
            *(float2*)&stage[row * ATG + col]       = make_float2(acc[mi][ni][0], acc[mi][ni][1]);
            *(float2*)&stage[(row + 8) * ATG + col] = make_float2(acc[mi][ni][2], acc[mi][ni][3]);
        }
    __syncthreads();

    const int b = bh >> 4, h = bh & 15;
#pragma unroll
    for (int i = 0; i < 8; i++) {
        const int e = tid + i * 256;
        const int r = e >> 4, c4 = (e & 15) * 4;
        float4 v = *(const float4*)&stage[r * ATG + c4];
        *(float4*)(g_att + ((size_t)(b * 1024) + q0 + r) * 1024 + h * 64 + c4) = v;
    }
}

// ---------------- LayerNorm ----------------
__global__ __launch_bounds__(256) void ln_kernel(const float* __restrict__ gg_,
                                                 const float* __restrict__ bta,
                                                 float* __restrict__ y)
{
    __shared__ float s1[8], s2[8];
    const int row = blockIdx.x, tid = threadIdx.x, lane = tid & 31, w = tid >> 5;
    const float* xr = g_fc + (size_t)row * 1024;

    float4 v = *(const float4*)(xr + tid * 4);
    float s = v.x + v.y + v.z + v.w;
    float q = v.x*v.x + v.y*v.y + v.z*v.z + v.w*v.w;
#pragma unroll
    for (int o = 16; o > 0; o >>= 1) {
        s += __shfl_xor_sync(0xffffffffu, s, o);
        q += __shfl_xor_sync(0xffffffffu, q, o);
    }
    if (lane == 0) { s1[w] = s; s2[w] = q; }
    __syncthreads();
    s = 0.0f; q = 0.0f;
#pragma unroll
    for (int i = 0; i < 8; i++) { s += s1[i]; q += s2[i]; }

    const float mu  = s * (1.0f / 1024.0f);
    const float var = q * (1.0f / 1024.0f) - mu * mu;
    const float rs  = rsqrtf(var + 1e-5f);

    float4 gv = *(const float4*)(gg_ + tid * 4);
    float4 bb = *(const float4*)(bta + tid * 4);
    float4 o;
    o.x = (v.x - mu) * rs * gv.x + bb.x;
    o.y = (v.y - mu) * rs * gv.y + bb.y;
    o.z = (v.z - mu) * rs * gv.z + bb.z;
    o.w = (v.w - mu) * rs * gv.w + bb.w;
    *(float4*)(y + (size_t)row * 1024 + tid * 4) = o;
}

// ---------------------------------------------------------------------------
extern "C" void kernel_launch(void* const* d_in, const int* in_sizes, int n_in,
                              void* d_out, int out_size)
{
    const float* query    = (const float*)d_in[0];
    const float* key      = (const float*)d_in[1];
    const float* value    = (const float*)d_in[2];
    const int*   mask     = (const int*)  d_in[3];
    const float* relation = (const float*)d_in[4];
    const float* Wq       = (const float*)d_in[5];
    const float* Wk       = (const float*)d_in[6];
    const float* Wv       = (const float*)d_in[7];
    const float* fc_w     = (const float*)d_in[8];
    const float* fc_b     = (const float*)d_in[9];
    const float* ln_g     = (const float*)d_in[10];
    const float* ln_b     = (const float*)d_in[11];

    float* y = (float*)d_out;
    float* p = y + (size_t)YSIZE;

    static bool attr_set = false;
    if (!attr_set) {
        cudaFuncSetAttribute(mma_gemm,   cudaFuncAttributeMaxDynamicSharedMemorySize, SM_G);
        cudaFuncSetAttribute(scores_mma, cudaFuncAttributeMaxDynamicSharedMemorySize, SM_S);
        cudaFuncSetAttribute(att_mma,    cudaFuncAttributeMaxDynamicSharedMemorySize, SM_A);
        attr_set = true;
    }

    dim3 tb(32, 8), tg(32, 32);
    transpose_w<<<tg, tb>>>(Wq, 0);
    transpose_w<<<tg, tb>>>(Wk, 1);
    transpose_w<<<tg, tb>>>(Wv, 2);
    transpose_w<<<tg, tb>>>(fc_w, 3);

    dim3 gg(8, 32);
    mma_gemm<<<gg, 256, SM_G>>>(query, 0, 0, nullptr, nullptr);   // launch 5
    mma_gemm<<<gg, 256, SM_G>>>(key,   1, 1, nullptr, nullptr);   // launch 6 (ncu target)
    mma_gemm<<<gg, 256, SM_G>>>(value, 2, 2, nullptr, nullptr);

    scores_mma<<<dim3(8, 8, 64), 256, SM_S>>>(relation, mask, p);
    combine_kernel<<<256, 256>>>();
    att_mma<<<dim3(8, 64), 256, SM_A>>>(p);

    mma_gemm<<<gg, 256, SM_G>>>(nullptr, 3, 3, fc_b, query);
    ln_kernel<<<Mc, 256>>>(ln_g, ln_b, y);
}

// round 7
// speedup vs baseline: 2.8416x; 1.1577x over previous
#include <cuda_runtime.h>
#include <math.h>
#include <stdint.h>

#define Bc   4
#define Sc   1024
#define Dc   1024
#define Hc   16
#define DKc  64
#define Mc   (Bc*Sc)        // 4096
#define BHc  (Bc*Hc)        // 64
#define YSIZE (Bc*Sc*Dc)

// ---------------- device scratch ----------------
__device__ float g_Q[Mc*Dc];        // [bh][s][dk]  (tf32-rounded)
__device__ float g_K[Mc*Dc];        // [bh][s][dk]  (tf32-rounded)
__device__ float g_VT[Mc*Dc];       // [bh][dk][s]  (tf32-rounded)
__device__ float g_att[Mc*Dc];      // [m][h*dk]    (tf32-rounded)
__device__ float g_fc[Mc*Dc];       // fc + resid (fp32)
__device__ float g_WT[4][Dc*Dc];    // WT[n][k]     (tf32-rounded)
__device__ float g_pmax[BHc*8*Sc];  // [bh][nt][q]
__device__ float g_psum[BHc*8*Sc];
__device__ float g_scale[BHc*8*Sc];

// ---------------- helpers ----------------
__device__ __forceinline__ uint32_t smem_u32(const void* p) {
    uint32_t a;
    asm("{ .reg .u64 t; cvta.to.shared.u64 t, %1; cvt.u32.u64 %0, t; }" : "=r"(a) : "l"(p));
    return a;
}
__device__ __forceinline__ float tf32r(float x) {
    uint32_t u;
    asm("cvt.rna.tf32.f32 %0, %1;" : "=r"(u) : "f"(x));
    return __uint_as_float(u);
}
__device__ __forceinline__ void mma_tf32(float* c, const float* a, const float* b) {
    asm volatile("mma.sync.aligned.m16n8k8.row.col.f32.tf32.tf32.f32 "
        "{%0,%1,%2,%3}, {%4,%5,%6,%7}, {%8,%9}, {%0,%1,%2,%3};"
        : "+f"(c[0]), "+f"(c[1]), "+f"(c[2]), "+f"(c[3])
        : "r"(__float_as_uint(a[0])), "r"(__float_as_uint(a[1])),
          "r"(__float_as_uint(a[2])), "r"(__float_as_uint(a[3])),
          "r"(__float_as_uint(b[0])), "r"(__float_as_uint(b[1])));
}
__device__ __forceinline__ void st4cvt(float* d, float4 v) {
    float4 o = make_float4(tf32r(v.x), tf32r(v.y), tf32r(v.z), tf32r(v.w));
    *(float4*)d = o;
}
__device__ __forceinline__ void cpa16(uint32_t dst, const float* src) {
    asm volatile("cp.async.cg.shared.global [%0], [%1], 16;" :: "r"(dst), "l"(src));
}
#define CP_COMMIT() asm volatile("cp.async.commit_group;" ::: "memory")
__device__ __forceinline__ void cp_wait(int n) {
    if (n == 0) asm volatile("cp.async.wait_group 0;" ::: "memory");
    else        asm volatile("cp.async.wait_group 1;" ::: "memory");
}

// ---------------- weight transpose: W[k][n] -> WT[n][k], tf32-rounded ----------------
__global__ void transpose_w(const float* __restrict__ W, int widx)
{
    __shared__ float t[32][33];
    float* o = g_WT[widx];
    const int k0 = blockIdx.y * 32, n0 = blockIdx.x * 32;
    const int tx = threadIdx.x, ty = threadIdx.y;   // 32 x 8
#pragma unroll
    for (int i = 0; i < 32; i += 8)
        t[ty + i][tx] = W[(size_t)(k0 + ty + i) * Dc + n0 + tx];
    __syncthreads();
#pragma unroll
    for (int i = 0; i < 32; i += 8)
        o[(size_t)(n0 + ty + i) * Dc + k0 + tx] = tf32r(t[tx][ty + i]);
}

// ===========================================================================
// tf32 GEMM: C[128x128] = A @ WT^T. A register-path (cvt), B via cp.async.
// mode 0: -> g_Q (rounded)   mode 1: -> g_K (rounded)
// mode 2: -> g_VT (rounded)  mode 3: A=g_att, -> g_fc (+bias+resid, fp32)
// ===========================================================================
#define GST 36
#define GTILE (128*GST*4)          // 18432 bytes
#define GBUF  (2*GTILE)            // 36864
#define SM_G  (2*GBUF)             // 73728
#define STG 132

__global__ __launch_bounds__(256, 2) void mma_gemm(const float* __restrict__ Ain,
                                                   int widx, int mode,
                                                   const float* __restrict__ bias,
                                                   const float* __restrict__ resid)
{
    extern __shared__ __align__(16) char smem[];
    const uint32_t sb = smem_u32(smem);
    const int tid  = threadIdx.x;
    const int lane = tid & 31;
    const int wid  = tid >> 5;
    const int wm   = wid >> 2;
    const int wn   = wid & 3;
    const int g    = lane >> 2;
    const int cc   = lane & 3;
    const int m0 = blockIdx.y * 128;
    const int n0 = blockIdx.x * 128;

    const float* A = (mode == 3) ? g_att : Ain;
    const float* B = g_WT[widx];

    const int fr = tid >> 3, fc = (tid & 7) * 4;
    const size_t gA = (size_t)(m0 + fr) * 1024 + fc;
    const size_t gB = (size_t)(n0 + fr) * 1024 + fc;
    const uint32_t sOffB = (fr * GST + fc) * 4;     // bytes
    const uint32_t sOffA = fr * GST + fc;           // floats

    float acc[4][4][4];
#pragma unroll
    for (int i = 0; i < 4; i++)
#pragma unroll
        for (int j = 0; j < 4; j++)
#pragma unroll
            for (int q = 0; q < 4; q++) acc[i][j][q] = 0.0f;

    float4 pa[4];
    // prologue: tile 0
#pragma unroll
    for (int j = 0; j < 4; j++)
        cpa16(sb + GTILE + sOffB + j * 32 * GST * 4, B + gB + (size_t)j * 32 * 1024);
    CP_COMMIT();
#pragma unroll
    for (int j = 0; j < 4; j++) pa[j] = *(const float4*)(A + gA + (size_t)j * 32 * 1024);
    {
        float* As = (float*)smem;
#pragma unroll
        for (int j = 0; j < 4; j++) st4cvt(As + sOffA + j * 32 * GST, pa[j]);
    }

    for (int kt = 0; kt < 32; kt++) {
        if (kt < 31) {
            const size_t ko = (size_t)(kt + 1) * 32;
            const uint32_t bb = sb + ((kt + 1) & 1) * GBUF;
#pragma unroll
            for (int j = 0; j < 4; j++)
                cpa16(bb + GTILE + sOffB + j * 32 * GST * 4, B + gB + ko + (size_t)j * 32 * 1024);
            CP_COMMIT();
#pragma unroll
            for (int j = 0; j < 4; j++) pa[j] = *(const float4*)(A + gA + ko + (size_t)j * 32 * 1024);
            cp_wait(1);
        } else {
            cp_wait(0);
        }
        __syncthreads();
        const float* As = (float*)(smem + (kt & 1) * GBUF);
        const float* Bs = As + GTILE / 4;
#pragma unroll
        for (int kk = 0; kk < 32; kk += 8) {
            float af[4][4], bf[4][2];
#pragma unroll
            for (int mi = 0; mi < 4; mi++) {
                const int row = wm * 64 + mi * 16 + g;
                af[mi][0] = As[row * GST + kk + cc];
                af[mi][1] = As[(row + 8) * GST + kk + cc];
                af[mi][2] = As[row * GST + kk + cc + 4];
                af[mi][3] = As[(row + 8) * GST + kk + cc + 4];
            }
#pragma unroll
            for (int ni = 0; ni < 4; ni++) {
                const int col = wn * 32 + ni * 8 + g;
                bf[ni][0] = Bs[col * GST + kk + cc];
                bf[ni][1] = Bs[col * GST + kk + cc + 4];
            }
#pragma unroll
            for (int mi = 0; mi < 4; mi++)
#pragma unroll
                for (int ni = 0; ni < 4; ni++)
                    mma_tf32(acc[mi][ni], af[mi], bf[ni]);
        }
        if (kt < 31) {
            float* As2 = (float*)(smem + ((kt + 1) & 1) * GBUF);
#pragma unroll
            for (int j = 0; j < 4; j++) st4cvt(As2 + sOffA + j * 32 * GST, pa[j]);
        }
        __syncthreads();
    }

    float* stage = (float*)smem;
#pragma unroll
    for (int mi = 0; mi < 4; mi++)
#pragma unroll
        for (int ni = 0; ni < 4; ni++) {
            const int row = wm * 64 + mi * 16 + (lane >> 2);
            const int col = wn * 32 + ni * 8 + (lane & 3) * 2;
            *(float2*)&stage[row * STG + col]       = make_float2(acc[mi][ni][0], acc[mi][ni][1]);
            *(float2*)&stage[(row + 8) * STG + col] = make_float2(acc[mi][ni][2], acc[mi][ni][3]);
        }
    __syncthreads();

    if (mode <= 1) {
        float* out = (mode == 0) ? g_Q : g_K;
#pragma unroll
        for (int i = 0; i < 16; i++) {
            const int e = tid + i * 256;
            const int r = e >> 5, c4 = (e & 31) * 4;
            float4 v = *(const float4*)&stage[r * STG + c4];
            const int m = m0 + r, b = m >> 10, s = m & 1023;
            const int n = n0 + c4, h = n >> 6, dk = n & 63;
            st4cvt(out + (((size_t)(b * 16 + h) * 1024 + s) * 64 + dk), v);
        }
    } else if (mode == 2) {
        const int r = tid & 127, half = tid >> 7;
        const int b = m0 >> 10, s0r = m0 & 1023;
#pragma unroll 8
        for (int j = 0; j < 64; j++) {
            const int c = half * 64 + j;
            const float v = stage[r * STG + c];
            const int n = n0 + c, hh = n >> 6, dk = n & 63;
            g_VT[((size_t)(b * 16 + hh) * 64 + dk) * 1024 + s0r + r] = tf32r(v);
        }
    } else {
#pragma unroll
        for (int i = 0; i < 16; i++) {
            const int e = tid + i * 256;
            const int r = e >> 5, c4 = (e & 31) * 4;
            float4 v = *(const float4*)&stage[r * STG + c4];
            const int m = m0 + r, n = n0 + c4;
            float4 bi = *(const float4*)(bias + n);
            float4 rs = *(const float4*)(resid + (size_t)m * 1024 + n);
            v.x += bi.x + rs.x; v.y += bi.y + rs.y;
            v.z += bi.z + rs.z; v.w += bi.w + rs.w;
            *(float4*)(g_fc + (size_t)m * 1024 + n) = v;
        }
    }
}

// ===========================================================================
// scores (tf32) + partial softmax. Q/K pre-rounded -> cp.async fill.
// CTA 128q x 128n, K=64. Grid (8,8,64).
// ===========================================================================
#define SST 68
#define SM_S (2*128*SST*4)          // 69632

__global__ __launch_bounds__(256, 2) void scores_mma(const float* __restrict__ rel,
                                                     const int*   __restrict__ mask,
                                                     float* __restrict__ p)
{
    extern __shared__ __align__(16) char smem[];
    const uint32_t sb = smem_u32(smem);
    float* Qs = (float*)smem;                 // [128][68]
    float* Ks = Qs + 128 * SST;

    const int tid = threadIdx.x, lane = tid & 31, wid = tid >> 5;
    const int wm = wid >> 2, wn = wid & 3;
    const int g = lane >> 2, cc = lane & 3;
    const int bh = blockIdx.z, q0 = blockIdx.y * 128, n0 = blockIdx.x * 128;
    const size_t base = (size_t)bh * Sc * DKc;

    {
        const int fr = tid >> 4, fc = (tid & 15) * 4;
#pragma unroll
        for (int j = 0; j < 8; j++) {
            const int r = fr + j * 16;
            cpa16(sb + (r * SST + fc) * 4,              g_Q + base + (size_t)(q0 + r) * 64 + fc);
            cpa16(sb + ((128 + r) * SST + fc) * 4,      g_K + base + (size_t)(n0 + r) * 64 + fc);
        }
        CP_COMMIT();
        cp_wait(0);
    }
    __syncthreads();

    float acc[4][4][4];
#pragma unroll
    for (int i = 0; i < 4; i++)
#pragma unroll
        for (int j = 0; j < 4; j++)
#pragma unroll
            for (int q = 0; q < 4; q++) acc[i][j][q] = 0.0f;

#pragma unroll
    for (int kk = 0; kk < 64; kk += 8) {
        float af[4][4], bf[4][2];
#pragma unroll
        for (int mi = 0; mi < 4; mi++) {
            const int row = wm * 64 + mi * 16 + g;
            af[mi][0] = Qs[row * SST + kk + cc];
            af[mi][1] = Qs[(row + 8) * SST + kk + cc];
            af[mi][2] = Qs[row * SST + kk + cc + 4];
            af[mi][3] = Qs[(row + 8) * SST + kk + cc + 4];
        }
#pragma unroll
        for (int ni = 0; ni < 4; ni++) {
            const int col = wn * 32 + ni * 8 + g;
            bf[ni][0] = Ks[col * SST + kk + cc];
            bf[ni][1] = Ks[col * SST + kk + cc + 4];
        }
#pragma unroll
        for (int mi = 0; mi < 4; mi++)
#pragma unroll
            for (int ni = 0; ni < 4; ni++)
                mma_tf32(acc[mi][ni], af[mi], bf[ni]);
    }
    __syncthreads();

    float* stage = (float*)smem;
#pragma unroll
    for (int mi = 0; mi < 4; mi++)
#pragma unroll
        for (int ni = 0; ni < 4; ni++) {
            const int row = wm * 64 + mi * 16 + (lane >> 2);
            const int col = wn * 32 + ni * 8 + (lane & 3) * 2;
            *(float2*)&stage[row * STG + col]       = make_float2(acc[mi][ni][0], acc[mi][ni][1]);
            *(float2*)&stage[(row + 8) * STG + col] = make_float2(acc[mi][ni][2], acc[mi][ni][3]);
        }
    __syncthreads();

    const int b = bh >> 4;
#pragma unroll
    for (int i = 0; i < 16; i++) {
        const int r = i * 8 + wid;
        const int q = q0 + r;
        const int n = n0 + lane * 4;
        float4 v = *(const float4*)&stage[r * STG + lane * 4];
        const size_t ridx = ((size_t)b * Sc + q) * Sc + n;
        float4 r4 = *(const float4*)(rel + ridx);
        int4   m4 = *(const int4*)(mask + ridx);
        float4 x;
        x.x = m4.x ? -1e9f : fmaf(v.x, 0.125f, r4.x);
        x.y = m4.y ? -1e9f : fmaf(v.y, 0.125f, r4.y);
        x.z = m4.z ? -1e9f : fmaf(v.z, 0.125f, r4.z);
        x.w = m4.w ? -1e9f : fmaf(v.w, 0.125f, r4.w);
        float mx = fmaxf(fmaxf(x.x, x.y), fmaxf(x.z, x.w));
#pragma unroll
        for (int o = 16; o > 0; o >>= 1) mx = fmaxf(mx, __shfl_xor_sync(0xffffffffu, mx, o));
        float4 e;
        e.x = __expf(x.x - mx); e.y = __expf(x.y - mx);
        e.z = __expf(x.z - mx); e.w = __expf(x.w - mx);
        float s = e.x + e.y + e.z + e.w;
#pragma unroll
        for (int o = 16; o > 0; o >>= 1) s += __shfl_xor_sync(0xffffffffu, s, o);
        *(float4*)(p + ((size_t)bh * Sc + q) * Sc + n) = e;
        if (lane == 0) {
            g_pmax[((size_t)bh * 8 + blockIdx.x) * Sc + q] = mx;
            g_psum[((size_t)bh * 8 + blockIdx.x) * Sc + q] = s;
        }
    }
}

// ---------------- combine: per-row softmax scale per n-tile ----------------
__global__ __launch_bounds__(256) void combine_kernel()
{
    const int row = blockIdx.x * 256 + threadIdx.x;
    const int bh = row >> 10, q = row & 1023;
    float pm[8], ps[8];
#pragma unroll
    for (int t = 0; t < 8; t++) {
        pm[t] = g_pmax[((size_t)bh * 8 + t) * Sc + q];
        ps[t] = g_psum[((size_t)bh * 8 + t) * Sc + q];
    }
    float rm = pm[0];
#pragma unroll
    for (int t = 1; t < 8; t++) rm = fmaxf(rm, pm[t]);
    float rs = 0.0f;
#pragma unroll
    for (int t = 0; t < 8; t++) rs += ps[t] * __expf(pm[t] - rm);
    const float inv = 1.0f / rs;
#pragma unroll
    for (int t = 0; t < 8; t++)
        g_scale[((size_t)bh * 8 + t) * Sc + q] = __expf(pm[t] - rm) * inv;
}

// ===========================================================================
// att (tf32): finalizes p in-place, att = P @ V. V via cp.async (pre-rounded).
// CTA 128q x 64dk, k-tiles of 32, double-buffered. Grid (8, 64).
// ===========================================================================
#define AST 36
#define AT_PB (128*AST*4)           // 18432
#define AT_VB (64*AST*4)            // 9216
#define AT_BUF (AT_PB+AT_VB)        // 27648
#define SM_A (2*AT_BUF + 1024)
#define ATG 68

__global__ __launch_bounds__(256, 2) void att_mma(float* __restrict__ p)
{
    extern __shared__ __align__(16) char smem[];
    const uint32_t sb = smem_u32(smem);
    float* sscale = (float*)(smem + 2 * AT_BUF);   // [2][128]

    const int tid = threadIdx.x, lane = tid & 31, wid = tid >> 5;
    const int wm = wid >> 1, wn = wid & 1;
    const int g = lane >> 2, cc = lane & 3;
    const int q0 = blockIdx.x * 128, bh = blockIdx.y;
    float* Pb = p + ((size_t)bh * 1024 + q0) * 1024;
    const float* Vb = g_VT + (size_t)bh * 64 * 1024;

    const int fr = tid >> 3, fc = (tid & 7) * 4;
    const uint32_t pOff = fr * AST + fc;             // floats (Ps)
    const uint32_t vOffB = (fr * AST + fc) * 4;      // bytes (within V region)

    float acc[2][4][4];
#pragma unroll
    for (int i = 0; i < 2; i++)
#pragma unroll
        for (int j = 0; j < 4; j++)
#pragma unroll
            for (int q = 0; q < 4; q++) acc[i][j][q] = 0.0f;

    float4 pa[4];

    // prologue
    if (tid < 128) sscale[tid] = g_scale[((size_t)bh * 8 + 0) * Sc + q0 + tid];
#pragma unroll
    for (int j = 0; j < 2; j++)
        cpa16(sb + AT_PB + vOffB + j * 32 * AST * 4, Vb + (size_t)(fr + 32 * j) * 1024 + fc);
    CP_COMMIT();
    __syncthreads();   // sscale visible
#pragma unroll
    for (int j = 0; j < 4; j++) pa[j] = *(const float4*)(Pb + (size_t)(fr + 32 * j) * 1024 + fc);
    {
        float* Ps = (float*)smem;
#pragma unroll
        for (int j = 0; j < 4; j++) {
            const float s = sscale[fr + 32 * j];
            float4 pf = make_float4(pa[j].x * s, pa[j].y * s, pa[j].z * s, pa[j].w * s);
            *(float4*)(Pb + (size_t)(fr + 32 * j) * 1024 + fc) = pf;   // final p
            st4cvt(Ps + pOff + j * 32 * AST, pf);
        }
    }

    for (int kt = 0; kt < 32; kt++) {
        const int ktn = kt + 1;
        if (kt < 31) {
            const size_t ko = (size_t)ktn * 32;
            const uint32_t bb = sb + (ktn & 1) * AT_BUF;
#pragma unroll
            for (int j = 0; j < 2; j++)
                cpa16(bb + AT_PB + vOffB + j * 32 * AST * 4, Vb + (size_t)(fr + 32 * j) * 1024 + ko + fc);
            CP_COMMIT();
#pragma unroll
            for (int j = 0; j < 4; j++) pa[j] = *(const float4*)(Pb + (size_t)(fr + 32 * j) * 1024 + ko + fc);
            if ((ktn & 3) == 0) {
                const int nt = ktn >> 2;
                if (tid < 128) sscale[(nt & 1) * 128 + tid] = g_scale[((size_t)bh * 8 + nt) * Sc + q0 + tid];
            }
            cp_wait(1);
        } else {
            cp_wait(0);
        }
        __syncthreads();
        const float* Ps = (float*)(smem + (kt & 1) * AT_BUF);
        const float* Vs = Ps + AT_PB / 4;
#pragma unroll
        for (int kk = 0; kk < 32; kk += 8) {
            float af[2][4], bf[4][2];
#pragma unroll
            for (int mi = 0; mi < 2; mi++) {
                const int row = wm * 32 + mi * 16 + g;
                af[mi][0] = Ps[row * AST + kk + cc];
                af[mi][1] = Ps[(row + 8) * AST + kk + cc];
                af[mi][2] = Ps[row * AST + kk + cc + 4];
                af[mi][3] = Ps[(row + 8) * AST + kk + cc + 4];
            }
#pragma unroll
            for (int ni = 0; ni < 4; ni++) {
                const int col = wn * 32 + ni * 8 + g;
                bf[ni][0] = Vs[col * AST + kk + cc];
                bf[ni][1] = Vs[col * AST + kk + cc + 4];
            }
#pragma unroll
            for (int mi = 0; mi < 2; mi++)
#pragma unroll
                for (int ni = 0; ni < 4; ni++)
                    mma_tf32(acc[mi][ni], af[mi], bf[ni]);
        }
        if (kt < 31) {
            float* Ps2 = (float*)(smem + (ktn & 1) * AT_BUF);
            const int nt = ktn >> 2;
            const float* sc = sscale + (nt & 1) * 128;
            const size_t ko = (size_t)ktn * 32;
#pragma unroll
            for (int j = 0; j < 4; j++) {
                const float s = sc[fr + 32 * j];
                float4 pf = make_float4(pa[j].x * s, pa[j].y * s, pa[j].z * s, pa[j].w * s);
                *(float4*)(Pb + (size_t)(fr + 32 * j) * 1024 + ko + fc) = pf;
                st4cvt(Ps2 + pOff + j * 32 * AST, pf);
            }
        }
        __syncthreads();
    }

    float* stage = (float*)smem;   // [128][68]
#pragma unroll
    for (int mi = 0; mi < 2; mi++)
#pragma unroll
        for (int ni = 0; ni < 4; ni++) {
            const int row = wm * 32 + mi * 16 + (lane >> 2);
            const int col = wn * 32 + ni * 8 + (lane & 3) * 2;
            *(float2*)&stage[row * ATG + col]       = make_float2(acc[mi][ni][0], acc[mi][ni][1]);
            *(float2*)&stage[(row + 8) * ATG + col] = make_float2(acc[mi][ni][2], acc[mi][ni][3]);
        }
    __syncthreads();

    const int b = bh >> 4, h = bh & 15;
#pragma unroll
    for (int i = 0; i < 8; i++) {
        const int e = tid + i * 256;
        const int r = e >> 4, c4 = (e & 15) * 4;
        float4 v = *(const float4*)&stage[r * ATG + c4];
        st4cvt(g_att + ((size_t)(b * 1024) + q0 + r) * 1024 + h * 64 + c4, v);
    }
}

// ---------------- LayerNorm ----------------
__global__ __launch_bounds__(256) void ln_kernel(const float* __restrict__ gg_,
                                                 const float* __restrict__ bta,
                                                 float* __restrict__ y)
{
    __shared__ float s1[8], s2[8];
    const int row = blockIdx.x, tid = threadIdx.x, lane = tid & 31, w = tid >> 5;
    const float* xr = g_fc + (size_t)row * 1024;

    float4 v = *(const float4*)(xr + tid * 4);
    float s = v.x + v.y + v.z + v.w;
    float q = v.x*v.x + v.y*v.y + v.z*v.z + v.w*v.w;
#pragma unroll
    for (int o = 16; o > 0; o >>= 1) {
        s += __shfl_xor_sync(0xffffffffu, s, o);
        q += __shfl_xor_sync(0xffffffffu, q, o);
    }
    if (lane == 0) { s1[w] = s; s2[w] = q; }
    __syncthreads();
    s = 0.0f; q = 0.0f;
#pragma unroll
    for (int i = 0; i < 8; i++) { s += s1[i]; q += s2[i]; }

    const float mu  = s * (1.0f / 1024.0f);
    const float var = q * (1.0f / 1024.0f) - mu * mu;
    const float rs  = rsqrtf(var + 1e-5f);

    float4 gv = *(const float4*)(gg_ + tid * 4);
    float4 bb = *(const float4*)(bta + tid * 4);
    float4 o;
    o.x = (v.x - mu) * rs * gv.x + bb.x;
    o.y = (v.y - mu) * rs * gv.y + bb.y;
    o.z = (v.z - mu) * rs * gv.z + bb.z;
    o.w = (v.w - mu) * rs * gv.w + bb.w;
    *(float4*)(y + (size_t)row * 1024 + tid * 4) = o;
}

// ---------------------------------------------------------------------------
extern "C" void kernel_launch(void* const* d_in, const int* in_sizes, int n_in,
                              void* d_out, int out_size)
{
    const float* query    = (const float*)d_in[0];
    const float* key      = (const float*)d_in[1];
    const float* value    = (const float*)d_in[2];
    const int*   mask     = (const int*)  d_in[3];
    const float* relation = (const float*)d_in[4];
    const float* Wq       = (const float*)d_in[5];
    const float* Wk       = (const float*)d_in[6];
    const float* Wv       = (const float*)d_in[7];
    const float* fc_w     = (const float*)d_in[8];
    const float* fc_b     = (const float*)d_in[9];
    const float* ln_g     = (const float*)d_in[10];
    const float* ln_b     = (const float*)d_in[11];

    float* y = (float*)d_out;
    float* p = y + (size_t)YSIZE;

    static bool attr_set = false;
    if (!attr_set) {
        cudaFuncSetAttribute(mma_gemm,   cudaFuncAttributeMaxDynamicSharedMemorySize, SM_G);
        cudaFuncSetAttribute(scores_mma, cudaFuncAttributeMaxDynamicSharedMemorySize, SM_S);
        cudaFuncSetAttribute(att_mma,    cudaFuncAttributeMaxDynamicSharedMemorySize, SM_A);
        attr_set = true;
    }

    dim3 tb(32, 8), tg(32, 32);
    transpose_w<<<tg, tb>>>(Wq, 0);
    transpose_w<<<tg, tb>>>(Wk, 1);
    transpose_w<<<tg, tb>>>(Wv, 2);
    transpose_w<<<tg, tb>>>(fc_w, 3);

    dim3 gg(8, 32);
    mma_gemm<<<gg, 256, SM_G>>>(query, 0, 0, nullptr, nullptr);   // launch 5
    mma_gemm<<<gg, 256, SM_G>>>(key,   1, 1, nullptr, nullptr);   // launch 6 (ncu target)
    mma_gemm<<<gg, 256, SM_G>>>(value, 2, 2, nullptr, nullptr);

    scores_mma<<<dim3(8, 8, 64), 256, SM_S>>>(relation, mask, p);
    combine_kernel<<<256, 256>>>();
    att_mma<<<dim3(8, 64), 256, SM_A>>>(p);

    mma_gemm<<<gg, 256, SM_G>>>(nullptr, 3, 3, fc_b, query);
    ln_kernel<<<Mc, 256>>>(ln_g, ln_b, y);
}